// round 1
// baseline (speedup 1.0000x reference)
#include <cuda_runtime.h>
#include <math.h>

#define BT   18464          // B*T
#define B_   32
#define T_   577
#define D_   768
#define H_   3072
#define NH   12
#define TT   332929         // T_*T_

// ---------------- static scratch (no allocations allowed) ----------------
__device__ float g_y  [(size_t)BT * D_];   // LN outputs
__device__ float g_qkv[(size_t)BT * 2304]; // qkv projections
__device__ float g_dp [(size_t)B_ * NH * TT]; // attention scores / probs
__device__ float g_wa [(size_t)BT * D_];   // attention out (B,T,h*dh)
__device__ float g_x1 [(size_t)BT * D_];   // residual after attention
__device__ float g_h  [(size_t)BT * H_];   // MLP hidden

// ---------------- LayerNorm: one block per row ----------------
__global__ void __launch_bounds__(256) ln_kernel(const float* __restrict__ x,
                                                 const float* __restrict__ w,
                                                 const float* __restrict__ b,
                                                 float* __restrict__ y) {
    const int row = blockIdx.x;
    const float* xr = x + (size_t)row * D_;
    float* yr = y + (size_t)row * D_;
    const int tid = threadIdx.x;

    float v0 = xr[tid], v1 = xr[tid + 256], v2 = xr[tid + 512];
    float s  = v0 + v1 + v2;
    float s2 = v0 * v0 + v1 * v1 + v2 * v2;
    #pragma unroll
    for (int o = 16; o > 0; o >>= 1) {
        s  += __shfl_xor_sync(0xffffffffu, s,  o);
        s2 += __shfl_xor_sync(0xffffffffu, s2, o);
    }
    __shared__ float sh[8], sh2[8];
    const int wi = tid >> 5, ln = tid & 31;
    if (ln == 0) { sh[wi] = s; sh2[wi] = s2; }
    __syncthreads();
    if (wi == 0) {
        s  = (ln < 8) ? sh[ln]  : 0.f;
        s2 = (ln < 8) ? sh2[ln] : 0.f;
        #pragma unroll
        for (int o = 4; o > 0; o >>= 1) {
            s  += __shfl_xor_sync(0xffffffffu, s,  o);
            s2 += __shfl_xor_sync(0xffffffffu, s2, o);
        }
        if (ln == 0) { sh[0] = s; sh2[0] = s2; }
    }
    __syncthreads();
    const float mu  = sh[0] * (1.0f / D_);
    const float var = sh2[0] * (1.0f / D_) - mu * mu;
    const float rs  = rsqrtf(var + 1e-6f);
    yr[tid]       = (v0 - mu) * rs * w[tid]       + b[tid];
    yr[tid + 256] = (v1 - mu) * rs * w[tid + 256] + b[tid + 256];
    yr[tid + 512] = (v2 - mu) * rs * w[tid + 512] + b[tid + 512];
}

// ---------------- Main GEMM: C = act(A@W + bias) [+ res] ----------------
// BM=128, BN=128, BK=16, 256 threads, 8x8 per thread.
// ACT: 0 = none, 1 = exact GELU.  RES: add residual (same shape as C).
template <int ACT, bool RES>
__global__ void __launch_bounds__(256, 2) gemm_kernel(
    const float* __restrict__ A, const float* __restrict__ W,
    const float* __restrict__ bias, const float* __restrict__ res,
    float* __restrict__ C, int M, int N, int K) {
    __shared__ float As[16][128];
    __shared__ float Bs[16][128];
    const int bm = blockIdx.y, bn = blockIdx.x;
    const int tid = threadIdx.x;
    const int tx = tid & 15, ty = tid >> 4;
    const int rowbase = bm * 128;

    float acc[8][8];
    #pragma unroll
    for (int i = 0; i < 8; i++)
        #pragma unroll
        for (int j = 0; j < 8; j++) acc[i][j] = 0.f;

    for (int k0 = 0; k0 < K; k0 += 16) {
        #pragma unroll
        for (int i = 0; i < 2; i++) {
            int idx = tid + i * 256;
            int ar = idx >> 2, ac = (idx & 3) << 2;
            int gr = rowbase + ar;
            float4 v = make_float4(0.f, 0.f, 0.f, 0.f);
            if (gr < M) v = *(const float4*)(A + (size_t)gr * K + k0 + ac);
            As[ac + 0][ar] = v.x; As[ac + 1][ar] = v.y;
            As[ac + 2][ar] = v.z; As[ac + 3][ar] = v.w;
        }
        #pragma unroll
        for (int i = 0; i < 2; i++) {
            int idx = tid + i * 256;
            int br = idx >> 5, bc = (idx & 31) << 2;
            *(float4*)&Bs[br][bc] =
                *(const float4*)(W + (size_t)(k0 + br) * N + bn * 128 + bc);
        }
        __syncthreads();
        #pragma unroll
        for (int k = 0; k < 16; k++) {
            float4 a0 = *(float4*)&As[k][ty * 8];
            float4 a1 = *(float4*)&As[k][ty * 8 + 4];
            float4 b0 = *(float4*)&Bs[k][tx * 8];
            float4 b1 = *(float4*)&Bs[k][tx * 8 + 4];
            float a[8] = {a0.x, a0.y, a0.z, a0.w, a1.x, a1.y, a1.z, a1.w};
            float b[8] = {b0.x, b0.y, b0.z, b0.w, b1.x, b1.y, b1.z, b1.w};
            #pragma unroll
            for (int i = 0; i < 8; i++)
                #pragma unroll
                for (int j = 0; j < 8; j++)
                    acc[i][j] = fmaf(a[i], b[j], acc[i][j]);
        }
        __syncthreads();
    }

    #pragma unroll
    for (int i = 0; i < 8; i++) {
        int gr = rowbase + ty * 8 + i;
        if (gr >= M) break;
        size_t ro = (size_t)gr * N + bn * 128 + tx * 8;
        #pragma unroll
        for (int j = 0; j < 8; j++) {
            float v = acc[i][j] + bias[bn * 128 + tx * 8 + j];
            if (ACT == 1) v = v * normcdff(v);  // exact GELU
            if (RES) v += res[ro + j];
            C[ro + j] = v;
        }
    }
}

// ---------------- Attention scores: dp[b,h,q,k] = scale * q.k ----------------
// grid: (ktile=10, qtile=10, bh=384), 256 threads, 4x4 per thread, full dh=64 in smem.
__global__ void __launch_bounds__(256) scores_kernel(const float* __restrict__ qkv,
                                                     float* __restrict__ dp) {
    const int bh = blockIdx.z;
    const int b = bh / NH, h = bh % NH;
    const int qt = blockIdx.y, kt = blockIdx.x;
    __shared__ float Qs[64][68];  // [d][q]
    __shared__ float Ks[64][68];  // [d][k]
    const int tid = threadIdx.x;

    #pragma unroll
    for (int i = 0; i < 4; i++) {
        int idx = tid + i * 256;
        int r = idx >> 4, c = (idx & 15) << 2;
        int t = qt * 64 + r;
        float4 v = make_float4(0.f, 0.f, 0.f, 0.f);
        if (t < T_) v = *(const float4*)(qkv + (size_t)(b * T_ + t) * 2304 + h * 64 + c);
        Qs[c + 0][r] = v.x; Qs[c + 1][r] = v.y; Qs[c + 2][r] = v.z; Qs[c + 3][r] = v.w;
    }
    #pragma unroll
    for (int i = 0; i < 4; i++) {
        int idx = tid + i * 256;
        int r = idx >> 4, c = (idx & 15) << 2;
        int t = kt * 64 + r;
        float4 v = make_float4(0.f, 0.f, 0.f, 0.f);
        if (t < T_) v = *(const float4*)(qkv + (size_t)(b * T_ + t) * 2304 + 768 + h * 64 + c);
        Ks[c + 0][r] = v.x; Ks[c + 1][r] = v.y; Ks[c + 2][r] = v.z; Ks[c + 3][r] = v.w;
    }
    __syncthreads();

    const int tx = tid & 15, ty = tid >> 4;
    float acc[4][4];
    #pragma unroll
    for (int i = 0; i < 4; i++)
        #pragma unroll
        for (int j = 0; j < 4; j++) acc[i][j] = 0.f;

    #pragma unroll
    for (int d = 0; d < 64; d++) {
        float4 a = *(float4*)&Qs[d][ty * 4];
        float4 bb = *(float4*)&Ks[d][tx * 4];
        float av[4] = {a.x, a.y, a.z, a.w};
        float bv[4] = {bb.x, bb.y, bb.z, bb.w};
        #pragma unroll
        for (int i = 0; i < 4; i++)
            #pragma unroll
            for (int j = 0; j < 4; j++)
                acc[i][j] = fmaf(av[i], bv[j], acc[i][j]);
    }

    #pragma unroll
    for (int i = 0; i < 4; i++) {
        int q = qt * 64 + ty * 4 + i;
        if (q >= T_) continue;
        size_t base = ((size_t)bh * T_ + q) * T_;
        #pragma unroll
        for (int j = 0; j < 4; j++) {
            int k = kt * 64 + tx * 4 + j;
            if (k < T_) dp[base + k] = acc[i][j] * 0.125f;
        }
    }
}

// ---------------- Softmax over HEADS axis (faithful to reference) ----------------
__global__ void softmax_h_kernel(float* __restrict__ dp) {
    long long idx = (long long)blockIdx.x * blockDim.x + threadIdx.x;
    if (idx >= (long long)B_ * TT) return;
    const int b = (int)(idx / TT);
    const int r = (int)(idx % TT);
    size_t base = (size_t)b * NH * TT + r;
    float v[NH];
    float mx = -1e30f;
    #pragma unroll
    for (int h = 0; h < NH; h++) {
        v[h] = dp[base + (size_t)h * TT];
        mx = fmaxf(mx, v[h]);
    }
    float s = 0.f;
    #pragma unroll
    for (int h = 0; h < NH; h++) { v[h] = expf(v[h] - mx); s += v[h]; }
    const float inv = 1.f / s;
    #pragma unroll
    for (int h = 0; h < NH; h++) dp[base + (size_t)h * TT] = v[h] * inv;
}

// ---------------- attn @ V  ->  wa in (B,T, h*64+d) layout ----------------
// grid: (qtile=10, 1, bh=384), 256 threads, 4x4 per thread, BK=32.
__global__ void __launch_bounds__(256) wa_kernel(const float* __restrict__ dp,
                                                 const float* __restrict__ qkv,
                                                 float* __restrict__ wa) {
    const int bh = blockIdx.z;
    const int b = bh / NH, h = bh % NH;
    const int qt = blockIdx.x;
    __shared__ float As[32][65];  // [k][q]
    __shared__ float Vs[32][64];  // [k][d]
    const int tid = threadIdx.x;
    const int tx = tid & 15, ty = tid >> 4;

    float acc[4][4];
    #pragma unroll
    for (int i = 0; i < 4; i++)
        #pragma unroll
        for (int j = 0; j < 4; j++) acc[i][j] = 0.f;

    for (int k0 = 0; k0 < T_; k0 += 32) {
        #pragma unroll
        for (int i = 0; i < 8; i++) {
            int idx = tid + i * 256;
            int qr = idx >> 5, kc = idx & 31;
            int q = qt * 64 + qr, k = k0 + kc;
            float v = 0.f;
            if (q < T_ && k < T_) v = dp[((size_t)bh * T_ + q) * T_ + k];
            As[kc][qr] = v;
        }
        #pragma unroll
        for (int i = 0; i < 2; i++) {
            int idx = tid + i * 256;
            int kr = idx >> 4, dc = (idx & 15) << 2;
            int k = k0 + kr;
            float4 v = make_float4(0.f, 0.f, 0.f, 0.f);
            if (k < T_) v = *(const float4*)(qkv + (size_t)(b * T_ + k) * 2304 + 1536 + h * 64 + dc);
            *(float4*)&Vs[kr][dc] = v;
        }
        __syncthreads();
        #pragma unroll
        for (int k = 0; k < 32; k++) {
            float a[4];
            #pragma unroll
            for (int i = 0; i < 4; i++) a[i] = As[k][ty * 4 + i];
            float4 vv = *(float4*)&Vs[k][tx * 4];
            float bv[4] = {vv.x, vv.y, vv.z, vv.w};
            #pragma unroll
            for (int i = 0; i < 4; i++)
                #pragma unroll
                for (int j = 0; j < 4; j++)
                    acc[i][j] = fmaf(a[i], bv[j], acc[i][j]);
        }
        __syncthreads();
    }

    #pragma unroll
    for (int i = 0; i < 4; i++) {
        int q = qt * 64 + ty * 4 + i;
        if (q >= T_) continue;
        #pragma unroll
        for (int j = 0; j < 4; j++)
            wa[(size_t)(b * T_ + q) * D_ + h * 64 + tx * 4 + j] = acc[i][j];
    }
}

// ---------------- host launch ----------------
extern "C" void kernel_launch(void* const* d_in, const int* in_sizes, int n_in,
                              void* d_out, int out_size) {
    const float* x      = (const float*)d_in[0];
    const float* ln1_w  = (const float*)d_in[1];
    const float* ln1_b  = (const float*)d_in[2];
    const float* qkv_w  = (const float*)d_in[3];
    const float* qkv_b  = (const float*)d_in[4];
    const float* proj_w = (const float*)d_in[5];
    const float* proj_b = (const float*)d_in[6];
    const float* ln2_w  = (const float*)d_in[7];
    const float* ln2_b  = (const float*)d_in[8];
    const float* fc1_w  = (const float*)d_in[9];
    const float* fc1_b  = (const float*)d_in[10];
    const float* fc2_w  = (const float*)d_in[11];
    const float* fc2_b  = (const float*)d_in[12];
    float* out = (float*)d_out;

    float *y, *qkvb, *dpb, *wab, *x1b, *hb;
    cudaGetSymbolAddress((void**)&y,    g_y);
    cudaGetSymbolAddress((void**)&qkvb, g_qkv);
    cudaGetSymbolAddress((void**)&dpb,  g_dp);
    cudaGetSymbolAddress((void**)&wab,  g_wa);
    cudaGetSymbolAddress((void**)&x1b,  g_x1);
    cudaGetSymbolAddress((void**)&hb,   g_h);

    const int MT = (BT + 127) / 128;  // 145

    // 1) LN1
    ln_kernel<<<BT, 256>>>(x, ln1_w, ln1_b, y);
    // 2) QKV projection
    gemm_kernel<0, false><<<dim3(2304 / 128, MT), 256>>>(y, qkv_w, qkv_b, nullptr, qkvb, BT, 2304, D_);
    // 3) scores
    scores_kernel<<<dim3(10, 10, B_ * NH), 256>>>(qkvb, dpb);
    // 4) softmax over heads
    {
        long long total = (long long)B_ * TT;
        int grid = (int)((total + 255) / 256);
        softmax_h_kernel<<<grid, 256>>>(dpb);
    }
    // 5) attn @ V
    wa_kernel<<<dim3(10, 1, B_ * NH), 256>>>(dpb, qkvb, wab);
    // 6) output projection + residual
    gemm_kernel<0, true><<<dim3(D_ / 128, MT), 256>>>(wab, proj_w, proj_b, x, x1b, BT, D_, D_);
    // 7) LN2
    ln_kernel<<<BT, 256>>>(x1b, ln2_w, ln2_b, y);
    // 8) fc1 + exact GELU
    gemm_kernel<1, false><<<dim3(H_ / 128, MT), 256>>>(y, fc1_w, fc1_b, nullptr, hb, BT, H_, D_);
    // 9) fc2 + residual -> output
    gemm_kernel<0, true><<<dim3(D_ / 128, MT), 256>>>(hb, fc2_w, fc2_b, x1b, out, BT, D_, H_);
}

// round 3
// speedup vs baseline: 1.6957x; 1.6957x over previous
#include <cuda_runtime.h>
#include <cuda_bf16.h>
#include <math.h>
#include <stdint.h>

#define BT   18464          // B*T
#define B_   32
#define T_   577
#define D_   768
#define H_   3072
#define NH   12
#define TT   332929         // T_*T_

// ---------------- static scratch ----------------
__device__ __nv_bfloat16 g_y_hi [(size_t)BT * D_];
__device__ __nv_bfloat16 g_y_lo [(size_t)BT * D_];
__device__ float         g_qkv  [(size_t)BT * 2304];
__device__ float         g_dp   [(size_t)B_ * NH * TT];
__device__ __nv_bfloat16 g_wa_hi[(size_t)BT * D_];
__device__ __nv_bfloat16 g_wa_lo[(size_t)BT * D_];
__device__ float         g_x1   [(size_t)BT * D_];
__device__ __nv_bfloat16 g_h_hi [(size_t)BT * H_];
__device__ __nv_bfloat16 g_h_lo [(size_t)BT * H_];
// transposed bf16-split weights [N,K]
__device__ __nv_bfloat16 g_wq_hi[2304 * 768], g_wq_lo[2304 * 768];
__device__ __nv_bfloat16 g_wp_hi[ 768 * 768], g_wp_lo[ 768 * 768];
__device__ __nv_bfloat16 g_w1_hi[3072 * 768], g_w1_lo[3072 * 768];
__device__ __nv_bfloat16 g_w2_hi[ 768 * 3072], g_w2_lo[ 768 * 3072];

// ---------------- helpers ----------------
__device__ __forceinline__ uint32_t smem_u32(const void* p) {
    uint32_t a;
    asm("{ .reg .u64 t; cvta.to.shared.u64 t, %1; cvt.u32.u64 %0, t; }" : "=r"(a) : "l"(p));
    return a;
}
__device__ __forceinline__ void cp16(uint32_t dst, const void* src) {
    asm volatile("cp.async.cg.shared.global [%0], [%1], 16;" :: "r"(dst), "l"(src));
}
#define CP_COMMIT() asm volatile("cp.async.commit_group;" ::: "memory")
#define CP_WAIT(n)  asm volatile("cp.async.wait_group %0;" :: "n"(n) : "memory")

__device__ __forceinline__ void ldsm4(uint32_t* r, uint32_t a) {
    asm volatile("ldmatrix.sync.aligned.m8n8.x4.shared.b16 {%0,%1,%2,%3}, [%4];"
                 : "=r"(r[0]), "=r"(r[1]), "=r"(r[2]), "=r"(r[3]) : "r"(a));
}
__device__ __forceinline__ void mma16816(float* c, const uint32_t* a, uint32_t b0, uint32_t b1) {
    asm volatile("mma.sync.aligned.m16n8k16.row.col.f32.bf16.bf16.f32 "
                 "{%0,%1,%2,%3}, {%4,%5,%6,%7}, {%8,%9}, {%0,%1,%2,%3};"
                 : "+f"(c[0]), "+f"(c[1]), "+f"(c[2]), "+f"(c[3])
                 : "r"(a[0]), "r"(a[1]), "r"(a[2]), "r"(a[3]), "r"(b0), "r"(b1));
}

// ---------------- weight transpose+split: W[K,N] fp32 -> [N,K] bf16 hi/lo ----------------
__global__ void wconv_kernel(const float* __restrict__ W,
                             __nv_bfloat16* __restrict__ hi,
                             __nv_bfloat16* __restrict__ lo, int K, int N) {
    __shared__ float t[32][33];
    const int k0 = blockIdx.y * 32, n0 = blockIdx.x * 32;
    #pragma unroll
    for (int i = 0; i < 4; i++)
        t[threadIdx.y + i * 8][threadIdx.x] =
            W[(size_t)(k0 + threadIdx.y + i * 8) * N + n0 + threadIdx.x];
    __syncthreads();
    #pragma unroll
    for (int i = 0; i < 4; i++) {
        int n = n0 + threadIdx.y + i * 8;
        int k = k0 + threadIdx.x;
        float x = t[threadIdx.x][threadIdx.y + i * 8];
        __nv_bfloat16 h = __float2bfloat16(x);
        hi[(size_t)n * K + k] = h;
        lo[(size_t)n * K + k] = __float2bfloat16(x - __bfloat162float(h));
    }
}

// ---------------- LayerNorm -> split bf16 ----------------
__global__ void __launch_bounds__(256) ln_kernel(const float* __restrict__ x,
                                                 const float* __restrict__ w,
                                                 const float* __restrict__ b,
                                                 __nv_bfloat16* __restrict__ yhi,
                                                 __nv_bfloat16* __restrict__ ylo) {
    const int row = blockIdx.x;
    const float* xr = x + (size_t)row * D_;
    const int tid = threadIdx.x;

    float v0 = xr[tid], v1 = xr[tid + 256], v2 = xr[tid + 512];
    float s  = v0 + v1 + v2;
    float s2 = v0 * v0 + v1 * v1 + v2 * v2;
    #pragma unroll
    for (int o = 16; o > 0; o >>= 1) {
        s  += __shfl_xor_sync(0xffffffffu, s,  o);
        s2 += __shfl_xor_sync(0xffffffffu, s2, o);
    }
    __shared__ float sh[8], sh2[8];
    const int wi = tid >> 5, ln = tid & 31;
    if (ln == 0) { sh[wi] = s; sh2[wi] = s2; }
    __syncthreads();
    if (wi == 0) {
        s  = (ln < 8) ? sh[ln]  : 0.f;
        s2 = (ln < 8) ? sh2[ln] : 0.f;
        #pragma unroll
        for (int o = 4; o > 0; o >>= 1) {
            s  += __shfl_xor_sync(0xffffffffu, s,  o);
            s2 += __shfl_xor_sync(0xffffffffu, s2, o);
        }
        if (ln == 0) { sh[0] = s; sh2[0] = s2; }
    }
    __syncthreads();
    const float mu  = sh[0] * (1.0f / D_);
    const float var = sh2[0] * (1.0f / D_) - mu * mu;
    const float rs  = rsqrtf(var + 1e-6f);
    size_t base = (size_t)row * D_;
    #pragma unroll
    for (int j = 0; j < 3; j++) {
        int c = tid + j * 256;
        float v = (j == 0 ? v0 : (j == 1 ? v1 : v2));
        float y = (v - mu) * rs * w[c] + b[c];
        __nv_bfloat16 h = __float2bfloat16(y);
        yhi[base + c] = h;
        ylo[base + c] = __float2bfloat16(y - __bfloat162float(h));
    }
}

// ---------------- HMMA GEMM: C = act(A @ W^T + bias) [+res] ----------------
// A: [M,K] bf16 split.  W: [N,K] bf16 split.  128x128 tile, BK=32, cp.async double buffer.
// SMEM stage layout (stride 80B rows): Ahi@0, Alo@10240, Bhi@20480, Blo@30720; stage size 40960.
template <int ACT, bool RES, bool OSPLIT>
__global__ void __launch_bounds__(256, 1) gemm_mma(
    const __nv_bfloat16* __restrict__ Ahi, const __nv_bfloat16* __restrict__ Alo,
    const __nv_bfloat16* __restrict__ Whi, const __nv_bfloat16* __restrict__ Wlo,
    const float* __restrict__ bias, const float* __restrict__ res,
    float* __restrict__ C, __nv_bfloat16* __restrict__ Chi, __nv_bfloat16* __restrict__ Clo,
    int M, int N, int K) {
    extern __shared__ char dsm[];
    const uint32_t sb = smem_u32(dsm);

    const int tid = threadIdx.x;
    const int lane = tid & 31, wid = tid >> 5;
    const int m0 = blockIdx.y * 128, n0 = blockIdx.x * 128;
    const int wm = (wid & 3) * 32, wn = (wid >> 2) * 64;

    // cp.async assignments: thread -> (row group, 16B quarter)
    const int lrow = tid >> 2;      // 0..63
    const int lq   = (tid & 3) * 16;

    // ldmatrix lane offsets
    const int mi = lane >> 3, r8 = lane & 7;
    const uint32_t aoff = (uint32_t)((wm + (mi & 1) * 8 + r8) * 80 + ((mi >> 1) * 8) * 2);
    const uint32_t boff = (uint32_t)((wn + (mi >> 1) * 8 + r8) * 80 + ((mi & 1) * 8) * 2);

    float acc[2][8][4];
    #pragma unroll
    for (int a = 0; a < 2; a++)
        #pragma unroll
        for (int b = 0; b < 8; b++)
            #pragma unroll
            for (int d = 0; d < 4; d++) acc[a][b][d] = 0.f;

    const int nc = K >> 5;

    // chunk loader
    auto load_chunk = [&](int c) {
        const uint32_t st = sb + (uint32_t)(c & 1) * 40960u;
        const int k0 = c << 5;
        #pragma unroll
        for (int i = 0; i < 2; i++) {
            int r = lrow + i * 64;
            int gr = m0 + r; if (gr > M - 1) gr = M - 1;
            size_t ga = (size_t)gr * K + k0;
            uint32_t d = st + (uint32_t)(r * 80) + lq;
            cp16(d,          (const char*)(Ahi + ga) + lq);
            cp16(d + 10240u, (const char*)(Alo + ga) + lq);
            size_t gb = (size_t)(n0 + r) * K + k0;
            cp16(d + 20480u, (const char*)(Whi + gb) + lq);
            cp16(d + 30720u, (const char*)(Wlo + gb) + lq);
        }
    };

    load_chunk(0);
    CP_COMMIT();

    for (int c = 0; c < nc; c++) {
        if (c + 1 < nc) {
            load_chunk(c + 1);
            CP_COMMIT();
            CP_WAIT(1);
        } else {
            CP_WAIT(0);
        }
        __syncthreads();

        const uint32_t st = sb + (uint32_t)(c & 1) * 40960u;
        #pragma unroll
        for (int kb = 0; kb < 2; kb++) {
            const uint32_t ko = (uint32_t)(kb * 32);  // 16 bf16 = 32 bytes
            uint32_t ah[2][4], al[2][4];
            ldsm4(ah[0], st + aoff + ko);
            ldsm4(ah[1], st + aoff + 1280u + ko);
            ldsm4(al[0], st + 10240u + aoff + ko);
            ldsm4(al[1], st + 10240u + aoff + 1280u + ko);
            #pragma unroll
            for (int p = 0; p < 4; p++) {
                uint32_t bh[4], bl[4];
                ldsm4(bh, st + 20480u + boff + (uint32_t)(p * 1280) + ko);
                ldsm4(bl, st + 30720u + boff + (uint32_t)(p * 1280) + ko);
                #pragma unroll
                for (int mt = 0; mt < 2; mt++) {
                    mma16816(acc[mt][2 * p],     ah[mt], bh[0], bh[1]);
                    mma16816(acc[mt][2 * p],     ah[mt], bl[0], bl[1]);
                    mma16816(acc[mt][2 * p],     al[mt], bh[0], bh[1]);
                    mma16816(acc[mt][2 * p + 1], ah[mt], bh[2], bh[3]);
                    mma16816(acc[mt][2 * p + 1], ah[mt], bl[2], bl[3]);
                    mma16816(acc[mt][2 * p + 1], al[mt], bh[2], bh[3]);
                }
            }
        }
        __syncthreads();
    }

    // ---------------- epilogue ----------------
    const int g = lane >> 2, tg = lane & 3;
    #pragma unroll
    for (int mt = 0; mt < 2; mt++) {
        const int rb = m0 + wm + mt * 16 + g;
        #pragma unroll
        for (int nt = 0; nt < 8; nt++) {
            const int col = n0 + wn + nt * 8 + tg * 2;
            const float bv0 = bias[col], bv1 = bias[col + 1];
            #pragma unroll
            for (int hh = 0; hh < 2; hh++) {
                const int row = rb + hh * 8;
                if (row < M) {
                    float v0 = acc[mt][nt][hh * 2]     + bv0;
                    float v1 = acc[mt][nt][hh * 2 + 1] + bv1;
                    if (ACT == 1) { v0 = v0 * normcdff(v0); v1 = v1 * normcdff(v1); }
                    size_t go = (size_t)row * N + col;
                    if (RES) {
                        float2 r2 = *(const float2*)(res + go);
                        v0 += r2.x; v1 += r2.y;
                    }
                    if (OSPLIT) {
                        __nv_bfloat162 h2, l2;
                        h2.x = __float2bfloat16(v0); h2.y = __float2bfloat16(v1);
                        l2.x = __float2bfloat16(v0 - __bfloat162float(h2.x));
                        l2.y = __float2bfloat16(v1 - __bfloat162float(h2.y));
                        *(__nv_bfloat162*)(Chi + go) = h2;
                        *(__nv_bfloat162*)(Clo + go) = l2;
                    } else {
                        *(float2*)(C + go) = make_float2(v0, v1);
                    }
                }
            }
        }
    }
}

// ---------------- Attention scores (SIMT fp32) ----------------
__global__ void __launch_bounds__(256) scores_kernel(const float* __restrict__ qkv,
                                                     float* __restrict__ dp) {
    const int bh = blockIdx.z;
    const int b = bh / NH, h = bh % NH;
    const int qt = blockIdx.y, kt = blockIdx.x;
    __shared__ float Qs[64][68];
    __shared__ float Ks[64][68];
    const int tid = threadIdx.x;

    #pragma unroll
    for (int i = 0; i < 4; i++) {
        int idx = tid + i * 256;
        int r = idx >> 4, c = (idx & 15) << 2;
        int t = qt * 64 + r;
        float4 v = make_float4(0.f, 0.f, 0.f, 0.f);
        if (t < T_) v = *(const float4*)(qkv + (size_t)(b * T_ + t) * 2304 + h * 64 + c);
        Qs[c + 0][r] = v.x; Qs[c + 1][r] = v.y; Qs[c + 2][r] = v.z; Qs[c + 3][r] = v.w;
    }
    #pragma unroll
    for (int i = 0; i < 4; i++) {
        int idx = tid + i * 256;
        int r = idx >> 4, c = (idx & 15) << 2;
        int t = kt * 64 + r;
        float4 v = make_float4(0.f, 0.f, 0.f, 0.f);
        if (t < T_) v = *(const float4*)(qkv + (size_t)(b * T_ + t) * 2304 + 768 + h * 64 + c);
        Ks[c + 0][r] = v.x; Ks[c + 1][r] = v.y; Ks[c + 2][r] = v.z; Ks[c + 3][r] = v.w;
    }
    __syncthreads();

    const int tx = tid & 15, ty = tid >> 4;
    float acc[4][4];
    #pragma unroll
    for (int i = 0; i < 4; i++)
        #pragma unroll
        for (int j = 0; j < 4; j++) acc[i][j] = 0.f;

    #pragma unroll
    for (int d = 0; d < 64; d++) {
        float4 a = *(float4*)&Qs[d][ty * 4];
        float4 bb = *(float4*)&Ks[d][tx * 4];
        float av[4] = {a.x, a.y, a.z, a.w};
        float bv[4] = {bb.x, bb.y, bb.z, bb.w};
        #pragma unroll
        for (int i = 0; i < 4; i++)
            #pragma unroll
            for (int j = 0; j < 4; j++)
                acc[i][j] = fmaf(av[i], bv[j], acc[i][j]);
    }

    #pragma unroll
    for (int i = 0; i < 4; i++) {
        int q = qt * 64 + ty * 4 + i;
        if (q >= T_) continue;
        size_t base = ((size_t)bh * T_ + q) * T_;
        #pragma unroll
        for (int j = 0; j < 4; j++) {
            int k = kt * 64 + tx * 4 + j;
            if (k < T_) dp[base + k] = acc[i][j] * 0.125f;
        }
    }
}

// ---------------- Softmax over HEADS axis ----------------
__global__ void softmax_h_kernel(float* __restrict__ dp) {
    long long idx = (long long)blockIdx.x * blockDim.x + threadIdx.x;
    if (idx >= (long long)B_ * TT) return;
    const int b = (int)(idx / TT);
    const int r = (int)(idx % TT);
    size_t base = (size_t)b * NH * TT + r;
    float v[NH];
    float mx = -1e30f;
    #pragma unroll
    for (int h = 0; h < NH; h++) {
        v[h] = dp[base + (size_t)h * TT];
        mx = fmaxf(mx, v[h]);
    }
    float s = 0.f;
    #pragma unroll
    for (int h = 0; h < NH; h++) { v[h] = expf(v[h] - mx); s += v[h]; }
    const float inv = 1.f / s;
    #pragma unroll
    for (int h = 0; h < NH; h++) dp[base + (size_t)h * TT] = v[h] * inv;
}

// ---------------- attn @ V -> wa (split bf16 output) ----------------
__global__ void __launch_bounds__(256) wa_kernel(const float* __restrict__ dp,
                                                 const float* __restrict__ qkv,
                                                 __nv_bfloat16* __restrict__ whi,
                                                 __nv_bfloat16* __restrict__ wlo) {
    const int bh = blockIdx.z;
    const int b = bh / NH, h = bh % NH;
    const int qt = blockIdx.x;
    __shared__ float As[32][65];
    __shared__ float Vs[32][64];
    const int tid = threadIdx.x;
    const int tx = tid & 15, ty = tid >> 4;

    float acc[4][4];
    #pragma unroll
    for (int i = 0; i < 4; i++)
        #pragma unroll
        for (int j = 0; j < 4; j++) acc[i][j] = 0.f;

    for (int k0 = 0; k0 < T_; k0 += 32) {
        #pragma unroll
        for (int i = 0; i < 8; i++) {
            int idx = tid + i * 256;
            int qr = idx >> 5, kc = idx & 31;
            int q = qt * 64 + qr, k = k0 + kc;
            float v = 0.f;
            if (q < T_ && k < T_) v = dp[((size_t)bh * T_ + q) * T_ + k];
            As[kc][qr] = v;
        }
        #pragma unroll
        for (int i = 0; i < 2; i++) {
            int idx = tid + i * 256;
            int kr = idx >> 4, dc = (idx & 15) << 2;
            int k = k0 + kr;
            float4 v = make_float4(0.f, 0.f, 0.f, 0.f);
            if (k < T_) v = *(const float4*)(qkv + (size_t)(b * T_ + k) * 2304 + 1536 + h * 64 + dc);
            *(float4*)&Vs[kr][dc] = v;
        }
        __syncthreads();
        #pragma unroll
        for (int k = 0; k < 32; k++) {
            float a[4];
            #pragma unroll
            for (int i = 0; i < 4; i++) a[i] = As[k][ty * 4 + i];
            float4 vv = *(float4*)&Vs[k][tx * 4];
            float bv[4] = {vv.x, vv.y, vv.z, vv.w};
            #pragma unroll
            for (int i = 0; i < 4; i++)
                #pragma unroll
                for (int j = 0; j < 4; j++)
                    acc[i][j] = fmaf(a[i], bv[j], acc[i][j]);
        }
        __syncthreads();
    }

    #pragma unroll
    for (int i = 0; i < 4; i++) {
        int q = qt * 64 + ty * 4 + i;
        if (q >= T_) continue;
        size_t go = (size_t)(b * T_ + q) * D_ + h * 64 + tx * 4;
        #pragma unroll
        for (int j = 0; j < 4; j++) {
            float v = acc[i][j];
            __nv_bfloat16 hh = __float2bfloat16(v);
            whi[go + j] = hh;
            wlo[go + j] = __float2bfloat16(v - __bfloat162float(hh));
        }
    }
}

// ---------------- host launch ----------------
extern "C" void kernel_launch(void* const* d_in, const int* in_sizes, int n_in,
                              void* d_out, int out_size) {
    const float* x      = (const float*)d_in[0];
    const float* ln1_w  = (const float*)d_in[1];
    const float* ln1_b  = (const float*)d_in[2];
    const float* qkv_w  = (const float*)d_in[3];
    const float* qkv_b  = (const float*)d_in[4];
    const float* proj_w = (const float*)d_in[5];
    const float* proj_b = (const float*)d_in[6];
    const float* ln2_w  = (const float*)d_in[7];
    const float* ln2_b  = (const float*)d_in[8];
    const float* fc1_w  = (const float*)d_in[9];
    const float* fc1_b  = (const float*)d_in[10];
    const float* fc2_w  = (const float*)d_in[11];
    const float* fc2_b  = (const float*)d_in[12];
    float* out = (float*)d_out;

    __nv_bfloat16 *yhi, *ylo, *wahi, *walo, *hhi, *hlo;
    __nv_bfloat16 *wqh, *wql, *wph, *wpl, *w1h, *w1l, *w2h, *w2l;
    float *qkvb, *dpb, *x1b;
    cudaGetSymbolAddress((void**)&yhi,  g_y_hi);
    cudaGetSymbolAddress((void**)&ylo,  g_y_lo);
    cudaGetSymbolAddress((void**)&qkvb, g_qkv);
    cudaGetSymbolAddress((void**)&dpb,  g_dp);
    cudaGetSymbolAddress((void**)&wahi, g_wa_hi);
    cudaGetSymbolAddress((void**)&walo, g_wa_lo);
    cudaGetSymbolAddress((void**)&x1b,  g_x1);
    cudaGetSymbolAddress((void**)&hhi,  g_h_hi);
    cudaGetSymbolAddress((void**)&hlo,  g_h_lo);
    cudaGetSymbolAddress((void**)&wqh,  g_wq_hi);
    cudaGetSymbolAddress((void**)&wql,  g_wq_lo);
    cudaGetSymbolAddress((void**)&wph,  g_wp_hi);
    cudaGetSymbolAddress((void**)&wpl,  g_wp_lo);
    cudaGetSymbolAddress((void**)&w1h,  g_w1_hi);
    cudaGetSymbolAddress((void**)&w1l,  g_w1_lo);
    cudaGetSymbolAddress((void**)&w2h,  g_w2_hi);
    cudaGetSymbolAddress((void**)&w2l,  g_w2_lo);

    const int SMEM_BYTES = 81920;
    cudaFuncSetAttribute(gemm_mma<0, false, false>, cudaFuncAttributeMaxDynamicSharedMemorySize, SMEM_BYTES);
    cudaFuncSetAttribute(gemm_mma<0, true,  false>, cudaFuncAttributeMaxDynamicSharedMemorySize, SMEM_BYTES);
    cudaFuncSetAttribute(gemm_mma<1, false, true >, cudaFuncAttributeMaxDynamicSharedMemorySize, SMEM_BYTES);

    const int MT = (BT + 127) / 128;  // 145

    // weight transpose + split
    wconv_kernel<<<dim3(2304 / 32, 768 / 32),  dim3(32, 8)>>>(qkv_w,  wqh, wql, 768,  2304);
    wconv_kernel<<<dim3(768 / 32,  768 / 32),  dim3(32, 8)>>>(proj_w, wph, wpl, 768,  768);
    wconv_kernel<<<dim3(3072 / 32, 768 / 32),  dim3(32, 8)>>>(fc1_w,  w1h, w1l, 768,  3072);
    wconv_kernel<<<dim3(768 / 32,  3072 / 32), dim3(32, 8)>>>(fc2_w,  w2h, w2l, 3072, 768);

    // 1) LN1 -> split
    ln_kernel<<<BT, 256>>>(x, ln1_w, ln1_b, yhi, ylo);
    // 2) QKV projection (HMMA)
    gemm_mma<0, false, false><<<dim3(2304 / 128, MT), 256, SMEM_BYTES>>>(
        yhi, ylo, wqh, wql, qkv_b, nullptr, qkvb, nullptr, nullptr, BT, 2304, D_);
    // 3) scores
    scores_kernel<<<dim3(10, 10, B_ * NH), 256>>>(qkvb, dpb);
    // 4) softmax over heads
    {
        long long total = (long long)B_ * TT;
        int grid = (int)((total + 255) / 256);
        softmax_h_kernel<<<grid, 256>>>(dpb);
    }
    // 5) attn @ V -> split
    wa_kernel<<<dim3(10, 1, B_ * NH), 256>>>(dpb, qkvb, wahi, walo);
    // 6) output projection + residual (HMMA)
    gemm_mma<0, true, false><<<dim3(D_ / 128, MT), 256, SMEM_BYTES>>>(
        wahi, walo, wph, wpl, proj_b, x, x1b, nullptr, nullptr, BT, D_, D_);
    // 7) LN2 -> split
    ln_kernel<<<BT, 256>>>(x1b, ln2_w, ln2_b, yhi, ylo);
    // 8) fc1 + exact GELU -> split output (HMMA)
    gemm_mma<1, false, true><<<dim3(H_ / 128, MT), 256, SMEM_BYTES>>>(
        yhi, ylo, w1h, w1l, fc1_b, nullptr, nullptr, hhi, hlo, BT, H_, D_);
    // 9) fc2 + residual -> output (HMMA)
    gemm_mma<0, true, false><<<dim3(D_ / 128, MT), 256, SMEM_BYTES>>>(
        hhi, hlo, w2h, w2l, fc2_b, x1b, out, nullptr, nullptr, BT, D_, H_);
}

// round 4
// speedup vs baseline: 2.2638x; 1.3350x over previous
#include <cuda_runtime.h>
#include <cuda_bf16.h>
#include <math.h>
#include <stdint.h>

#define BT   18464          // B*T
#define B_   32
#define T_   577
#define D_   768
#define H_   3072
#define NH   12
#define KPAD 584            // padded key dim for dp/probs rows (16B-aligned)
#define PTT  (T_ * KPAD)    // 336968, per-(b,h) plane size

// ---------------- static scratch ----------------
__device__ __nv_bfloat16 g_y_hi [(size_t)BT * D_];
__device__ __nv_bfloat16 g_y_lo [(size_t)BT * D_];
__device__ __nv_bfloat16 g_qkv_hi[(size_t)BT * 2304];
__device__ __nv_bfloat16 g_qkv_lo[(size_t)BT * 2304];
__device__ float         g_dp   [(size_t)B_ * NH * PTT];
__device__ __nv_bfloat16 g_p_hi [(size_t)B_ * NH * PTT];
__device__ __nv_bfloat16 g_p_lo [(size_t)B_ * NH * PTT];
__device__ __nv_bfloat16 g_wa_hi[(size_t)BT * D_];
__device__ __nv_bfloat16 g_wa_lo[(size_t)BT * D_];
__device__ float         g_x1   [(size_t)BT * D_];
__device__ __nv_bfloat16 g_h_hi [(size_t)BT * H_];
__device__ __nv_bfloat16 g_h_lo [(size_t)BT * H_];
__device__ __nv_bfloat16 g_wq_hi[2304 * 768], g_wq_lo[2304 * 768];
__device__ __nv_bfloat16 g_wp_hi[ 768 * 768], g_wp_lo[ 768 * 768];
__device__ __nv_bfloat16 g_w1_hi[3072 * 768], g_w1_lo[3072 * 768];
__device__ __nv_bfloat16 g_w2_hi[ 768 * 3072], g_w2_lo[ 768 * 3072];

// ---------------- helpers ----------------
__device__ __forceinline__ uint32_t smem_u32(const void* p) {
    uint32_t a;
    asm("{ .reg .u64 t; cvta.to.shared.u64 t, %1; cvt.u32.u64 %0, t; }" : "=r"(a) : "l"(p));
    return a;
}
__device__ __forceinline__ void cp16(uint32_t dst, const void* src) {
    asm volatile("cp.async.cg.shared.global [%0], [%1], 16;" :: "r"(dst), "l"(src));
}
__device__ __forceinline__ void cp16z(uint32_t dst, const void* src, int nb) {
    asm volatile("cp.async.cg.shared.global [%0], [%1], 16, %2;" :: "r"(dst), "l"(src), "r"(nb));
}
#define CP_COMMIT() asm volatile("cp.async.commit_group;" ::: "memory")
#define CP_WAIT(n)  asm volatile("cp.async.wait_group %0;" :: "n"(n) : "memory")

__device__ __forceinline__ void ldsm4(uint32_t* r, uint32_t a) {
    asm volatile("ldmatrix.sync.aligned.m8n8.x4.shared.b16 {%0,%1,%2,%3}, [%4];"
                 : "=r"(r[0]), "=r"(r[1]), "=r"(r[2]), "=r"(r[3]) : "r"(a));
}
__device__ __forceinline__ void ldsm4t(uint32_t* r, uint32_t a) {
    asm volatile("ldmatrix.sync.aligned.m8n8.x4.trans.shared.b16 {%0,%1,%2,%3}, [%4];"
                 : "=r"(r[0]), "=r"(r[1]), "=r"(r[2]), "=r"(r[3]) : "r"(a));
}
__device__ __forceinline__ void mma16816(float* c, const uint32_t* a, uint32_t b0, uint32_t b1) {
    asm volatile("mma.sync.aligned.m16n8k16.row.col.f32.bf16.bf16.f32 "
                 "{%0,%1,%2,%3}, {%4,%5,%6,%7}, {%8,%9}, {%0,%1,%2,%3};"
                 : "+f"(c[0]), "+f"(c[1]), "+f"(c[2]), "+f"(c[3])
                 : "r"(a[0]), "r"(a[1]), "r"(a[2]), "r"(a[3]), "r"(b0), "r"(b1));
}

// ---------------- weight transpose+split ----------------
__global__ void wconv_kernel(const float* __restrict__ W,
                             __nv_bfloat16* __restrict__ hi,
                             __nv_bfloat16* __restrict__ lo, int K, int N) {
    __shared__ float t[32][33];
    const int k0 = blockIdx.y * 32, n0 = blockIdx.x * 32;
    #pragma unroll
    for (int i = 0; i < 4; i++)
        t[threadIdx.y + i * 8][threadIdx.x] =
            W[(size_t)(k0 + threadIdx.y + i * 8) * N + n0 + threadIdx.x];
    __syncthreads();
    #pragma unroll
    for (int i = 0; i < 4; i++) {
        int n = n0 + threadIdx.y + i * 8;
        int k = k0 + threadIdx.x;
        float x = t[threadIdx.x][threadIdx.y + i * 8];
        __nv_bfloat16 h = __float2bfloat16(x);
        hi[(size_t)n * K + k] = h;
        lo[(size_t)n * K + k] = __float2bfloat16(x - __bfloat162float(h));
    }
}

// ---------------- LayerNorm -> split bf16 ----------------
__global__ void __launch_bounds__(256) ln_kernel(const float* __restrict__ x,
                                                 const float* __restrict__ w,
                                                 const float* __restrict__ b,
                                                 __nv_bfloat16* __restrict__ yhi,
                                                 __nv_bfloat16* __restrict__ ylo) {
    const int row = blockIdx.x;
    const float* xr = x + (size_t)row * D_;
    const int tid = threadIdx.x;

    float v0 = xr[tid], v1 = xr[tid + 256], v2 = xr[tid + 512];
    float s  = v0 + v1 + v2;
    float s2 = v0 * v0 + v1 * v1 + v2 * v2;
    #pragma unroll
    for (int o = 16; o > 0; o >>= 1) {
        s  += __shfl_xor_sync(0xffffffffu, s,  o);
        s2 += __shfl_xor_sync(0xffffffffu, s2, o);
    }
    __shared__ float sh[8], sh2[8];
    const int wi = tid >> 5, ln = tid & 31;
    if (ln == 0) { sh[wi] = s; sh2[wi] = s2; }
    __syncthreads();
    if (wi == 0) {
        s  = (ln < 8) ? sh[ln]  : 0.f;
        s2 = (ln < 8) ? sh2[ln] : 0.f;
        #pragma unroll
        for (int o = 4; o > 0; o >>= 1) {
            s  += __shfl_xor_sync(0xffffffffu, s,  o);
            s2 += __shfl_xor_sync(0xffffffffu, s2, o);
        }
        if (ln == 0) { sh[0] = s; sh2[0] = s2; }
    }
    __syncthreads();
    const float mu  = sh[0] * (1.0f / D_);
    const float var = sh2[0] * (1.0f / D_) - mu * mu;
    const float rs  = rsqrtf(var + 1e-6f);
    size_t base = (size_t)row * D_;
    #pragma unroll
    for (int j = 0; j < 3; j++) {
        int c = tid + j * 256;
        float v = (j == 0 ? v0 : (j == 1 ? v1 : v2));
        float y = (v - mu) * rs * w[c] + b[c];
        __nv_bfloat16 h = __float2bfloat16(y);
        yhi[base + c] = h;
        ylo[base + c] = __float2bfloat16(y - __bfloat162float(h));
    }
}

// ---------------- shared HMMA GEMM core: 128x128 tile, BK=32, 3-stage cp.async ----------------
// A:[M,?]@lda bf16 split, B:[N,?]@ldb bf16 split (both k-contiguous). 3-product bf16 split.
#define STG 40960u
template <int ACT, bool RES, bool OSPLIT, bool BIAS>
__device__ __forceinline__ void gemm_core(
    const __nv_bfloat16* __restrict__ Ahi, const __nv_bfloat16* __restrict__ Alo, size_t lda,
    const __nv_bfloat16* __restrict__ Bhp, const __nv_bfloat16* __restrict__ Blp, size_t ldb,
    const float* __restrict__ bias, const float* __restrict__ res,
    float* __restrict__ C, __nv_bfloat16* __restrict__ Chi, __nv_bfloat16* __restrict__ Clo,
    size_t ldc, int M, int N, int K, int m0, int n0, float scale, char* dsm)
{
    const uint32_t sb = smem_u32(dsm);
    const int tid = threadIdx.x;
    const int lane = tid & 31, wid = tid >> 5;
    const int wm = (wid & 3) * 32, wn = (wid >> 2) * 64;
    const int lrow = tid >> 2;
    const int lq   = (tid & 3) * 16;
    const int mi = lane >> 3, r8 = lane & 7;
    const uint32_t aoff = (uint32_t)((wm + (mi & 1) * 8 + r8) * 80 + ((mi >> 1) * 8) * 2);
    const uint32_t boff = (uint32_t)((wn + (mi >> 1) * 8 + r8) * 80 + ((mi & 1) * 8) * 2);

    float acc[2][8][4];
    #pragma unroll
    for (int a = 0; a < 2; a++)
        #pragma unroll
        for (int b = 0; b < 8; b++)
            #pragma unroll
            for (int d = 0; d < 4; d++) acc[a][b][d] = 0.f;

    const int nc = K >> 5;

    auto load_chunk = [&](int c) {
        const uint32_t st = sb + (uint32_t)(c % 3) * STG;
        const int k0 = c << 5;
        #pragma unroll
        for (int i = 0; i < 2; i++) {
            int r = lrow + i * 64;
            int gr = m0 + r; if (gr > M - 1) gr = M - 1;
            int gn = n0 + r; if (gn > N - 1) gn = N - 1;
            uint32_t d = st + (uint32_t)(r * 80) + lq;
            cp16(d,          (const char*)(Ahi + (size_t)gr * lda + k0) + lq);
            cp16(d + 10240u, (const char*)(Alo + (size_t)gr * lda + k0) + lq);
            cp16(d + 20480u, (const char*)(Bhp + (size_t)gn * ldb + k0) + lq);
            cp16(d + 30720u, (const char*)(Blp + (size_t)gn * ldb + k0) + lq);
        }
    };

    load_chunk(0); CP_COMMIT();
    if (nc > 1) load_chunk(1);
    CP_COMMIT();

    for (int c = 0; c < nc; c++) {
        CP_WAIT(1);
        __syncthreads();
        const uint32_t st = sb + (uint32_t)(c % 3) * STG;
        #pragma unroll
        for (int kb = 0; kb < 2; kb++) {
            const uint32_t ko = (uint32_t)(kb * 32);
            uint32_t ah[2][4], al[2][4];
            ldsm4(ah[0], st + aoff + ko);
            ldsm4(ah[1], st + aoff + 1280u + ko);
            ldsm4(al[0], st + 10240u + aoff + ko);
            ldsm4(al[1], st + 10240u + aoff + 1280u + ko);
            #pragma unroll
            for (int p = 0; p < 4; p++) {
                uint32_t bh[4], bl[4];
                ldsm4(bh, st + 20480u + boff + (uint32_t)(p * 1280) + ko);
                ldsm4(bl, st + 30720u + boff + (uint32_t)(p * 1280) + ko);
                #pragma unroll
                for (int mt = 0; mt < 2; mt++) {
                    mma16816(acc[mt][2 * p],     ah[mt], bh[0], bh[1]);
                    mma16816(acc[mt][2 * p],     ah[mt], bl[0], bl[1]);
                    mma16816(acc[mt][2 * p],     al[mt], bh[0], bh[1]);
                    mma16816(acc[mt][2 * p + 1], ah[mt], bh[2], bh[3]);
                    mma16816(acc[mt][2 * p + 1], ah[mt], bl[2], bl[3]);
                    mma16816(acc[mt][2 * p + 1], al[mt], bh[2], bh[3]);
                }
            }
        }
        if (c + 2 < nc) load_chunk(c + 2);
        CP_COMMIT();
    }

    // epilogue
    const int g = lane >> 2, tg = lane & 3;
    #pragma unroll
    for (int mt = 0; mt < 2; mt++) {
        const int rb = m0 + wm + mt * 16 + g;
        #pragma unroll
        for (int nt = 0; nt < 8; nt++) {
            const int col = n0 + wn + nt * 8 + tg * 2;
            float bv0 = 0.f, bv1 = 0.f;
            if (BIAS) { bv0 = bias[col]; bv1 = bias[col + 1]; }
            #pragma unroll
            for (int hh = 0; hh < 2; hh++) {
                const int row = rb + hh * 8;
                if (row < M) {
                    float v0 = acc[mt][nt][hh * 2]     * scale + bv0;
                    float v1 = acc[mt][nt][hh * 2 + 1] * scale + bv1;
                    if (ACT == 1) { v0 = v0 * normcdff(v0); v1 = v1 * normcdff(v1); }
                    size_t go = (size_t)row * ldc + col;
                    if (RES) {
                        float2 r2 = *(const float2*)(res + go);
                        v0 += r2.x; v1 += r2.y;
                    }
                    if (OSPLIT) {
                        __nv_bfloat162 h2, l2;
                        h2.x = __float2bfloat16(v0); h2.y = __float2bfloat16(v1);
                        l2.x = __float2bfloat16(v0 - __bfloat162float(h2.x));
                        l2.y = __float2bfloat16(v1 - __bfloat162float(h2.y));
                        *(__nv_bfloat162*)(Chi + go) = h2;
                        *(__nv_bfloat162*)(Clo + go) = l2;
                    } else {
                        if (col + 1 < N) *(float2*)(C + go) = make_float2(v0, v1);
                        else if (col < N) C[go] = v0;
                    }
                }
            }
        }
    }
}

// ---------------- linear GEMM wrapper ----------------
template <int ACT, bool RES, bool OSPLIT>
__global__ void __launch_bounds__(256, 1) gemm_lin(
    const __nv_bfloat16* __restrict__ Ahi, const __nv_bfloat16* __restrict__ Alo,
    const __nv_bfloat16* __restrict__ Whi, const __nv_bfloat16* __restrict__ Wlo,
    const float* __restrict__ bias, const float* __restrict__ res,
    float* __restrict__ C, __nv_bfloat16* __restrict__ Chi, __nv_bfloat16* __restrict__ Clo,
    int M, int N, int K) {
    extern __shared__ char dsm[];
    gemm_core<ACT, RES, OSPLIT, true>(Ahi, Alo, (size_t)K, Whi, Wlo, (size_t)K,
                                      bias, res, C, Chi, Clo, (size_t)N,
                                      M, N, K, blockIdx.y * 128, blockIdx.x * 128, 1.f, dsm);
}

// ---------------- attention scores wrapper (dp = 0.125 * q k^T) ----------------
__global__ void __launch_bounds__(256, 1) scores_mma(
    const __nv_bfloat16* __restrict__ qkvh, const __nv_bfloat16* __restrict__ qkvl,
    float* __restrict__ dp) {
    extern __shared__ char dsm[];
    const int bh = blockIdx.z;
    const int b = bh / NH, h = bh % NH;
    const size_t rbase = (size_t)b * T_ * 2304 + h * 64;
    gemm_core<0, false, false, false>(
        qkvh + rbase, qkvl + rbase, 2304,
        qkvh + rbase + 768, qkvl + rbase + 768, 2304,
        nullptr, nullptr,
        dp + (size_t)bh * PTT, nullptr, nullptr, (size_t)KPAD,
        T_, T_, 64, blockIdx.y * 128, blockIdx.x * 128, 0.125f, dsm);
}

// ---------------- softmax over HEADS -> split bf16 probs ----------------
__global__ void softmax_split(const float* __restrict__ dp,
                              __nv_bfloat16* __restrict__ phi,
                              __nv_bfloat16* __restrict__ plo) {
    long long idx = (long long)blockIdx.x * blockDim.x + threadIdx.x;
    if (idx >= (long long)B_ * PTT) return;
    const int b = (int)(idx / PTT);
    const int r = (int)(idx % PTT);
    size_t base = (size_t)b * NH * PTT + r;
    float v[NH];
    float mx = -1e30f;
    #pragma unroll
    for (int h = 0; h < NH; h++) {
        v[h] = dp[base + (size_t)h * PTT];
        mx = fmaxf(mx, v[h]);
    }
    float s = 0.f;
    #pragma unroll
    for (int h = 0; h < NH; h++) { v[h] = expf(v[h] - mx); s += v[h]; }
    const float inv = 1.f / s;
    #pragma unroll
    for (int h = 0; h < NH; h++) {
        float p = v[h] * inv;
        __nv_bfloat16 hh = __float2bfloat16(p);
        phi[base + (size_t)h * PTT] = hh;
        plo[base + (size_t)h * PTT] = __float2bfloat16(p - __bfloat162float(hh));
    }
}

// ---------------- wa = probs @ V (HMMA, ldmatrix.trans for V) ----------------
// CTA: 128q x 64d, 8 warps (4x2): warp 32q x 32d. K-chunks of 32, 3-stage pipeline.
#define STGW 29696u
__global__ void __launch_bounds__(256, 1) wa_mma(
    const __nv_bfloat16* __restrict__ phi, const __nv_bfloat16* __restrict__ plo,
    const __nv_bfloat16* __restrict__ qkvh, const __nv_bfloat16* __restrict__ qkvl,
    __nv_bfloat16* __restrict__ whi, __nv_bfloat16* __restrict__ wlo) {
    extern __shared__ char dsm[];
    const uint32_t sb = smem_u32(dsm);
    const int tid = threadIdx.x;
    const int lane = tid & 31, wid = tid >> 5;
    const int bh = blockIdx.y;
    const int b = bh / NH, h = bh % NH;
    const int q0 = blockIdx.x * 128;
    const int wm = (wid & 3) * 32, wn = (wid >> 2) * 32;
    const int lrow = tid >> 2;
    const int lq   = (tid & 3) * 16;
    const int mi = lane >> 3, r8 = lane & 7;
    const uint32_t aoff = (uint32_t)((wm + (mi & 1) * 8 + r8) * 80 + ((mi >> 1) * 8) * 2);
    const uint32_t voff = (uint32_t)(((mi & 1) * 8 + r8) * 144 + (wn + (mi >> 1) * 8) * 2);

    const size_t pbase = (size_t)bh * PTT;
    const size_t vbase = (size_t)b * T_ * 2304 + 1536 + h * 64;

    float acc[2][4][4];
    #pragma unroll
    for (int a = 0; a < 2; a++)
        #pragma unroll
        for (int n = 0; n < 4; n++)
            #pragma unroll
            for (int d = 0; d < 4; d++) acc[a][n][d] = 0.f;

    const int nc = (T_ + 31) / 32;  // 19

    auto load_chunk = [&](int c) {
        const uint32_t st = sb + (uint32_t)(c % 3) * STGW;
        const int k0 = c * 32;
        // probs tiles
        #pragma unroll
        for (int i = 0; i < 2; i++) {
            int r = lrow + i * 64;
            int q = q0 + r; if (q > T_ - 1) q = T_ - 1;
            int kstart = k0 + (lq >> 1);
            int nb = (T_ - kstart) * 2;
            nb = nb < 0 ? 0 : (nb > 16 ? 16 : nb);
            size_t off = pbase + (size_t)q * KPAD + k0;
            uint32_t d = st + (uint32_t)(r * 80) + lq;
            cp16z(d,          (const char*)(phi + off) + lq, nb);
            cp16z(d + 10240u, (const char*)(plo + off) + lq, nb);
        }
        // V tiles [32k][64d], stride 144
        {
            int vr = tid >> 3, vq = (tid & 7) * 16;
            int k = k0 + vr;
            int nb = (k < T_) ? 16 : 0;
            if (k > T_ - 1) k = T_ - 1;
            size_t off = vbase + (size_t)k * 2304;
            uint32_t d = st + 20480u + (uint32_t)(vr * 144) + vq;
            cp16z(d,         (const char*)(qkvh + off) + vq, nb);
            cp16z(d + 4608u, (const char*)(qkvl + off) + vq, nb);
        }
    };

    load_chunk(0); CP_COMMIT();
    load_chunk(1); CP_COMMIT();

    for (int c = 0; c < nc; c++) {
        CP_WAIT(1);
        __syncthreads();
        const uint32_t st = sb + (uint32_t)(c % 3) * STGW;
        #pragma unroll
        for (int ks = 0; ks < 2; ks++) {
            const uint32_t ko = (uint32_t)(ks * 32);
            uint32_t ah[2][4], al[2][4];
            ldsm4(ah[0], st + aoff + ko);
            ldsm4(ah[1], st + aoff + 1280u + ko);
            ldsm4(al[0], st + 10240u + aoff + ko);
            ldsm4(al[1], st + 10240u + aoff + 1280u + ko);
            uint32_t vh0[4], vh1[4], vl0[4], vl1[4];
            const uint32_t vb = st + 20480u + voff + (uint32_t)(ks * 2304);
            ldsm4t(vh0, vb);
            ldsm4t(vh1, vb + 32u);
            ldsm4t(vl0, vb + 4608u);
            ldsm4t(vl1, vb + 4608u + 32u);
            #pragma unroll
            for (int mt = 0; mt < 2; mt++) {
                mma16816(acc[mt][0], ah[mt], vh0[0], vh0[1]);
                mma16816(acc[mt][0], ah[mt], vl0[0], vl0[1]);
                mma16816(acc[mt][0], al[mt], vh0[0], vh0[1]);
                mma16816(acc[mt][1], ah[mt], vh0[2], vh0[3]);
                mma16816(acc[mt][1], ah[mt], vl0[2], vl0[3]);
                mma16816(acc[mt][1], al[mt], vh0[2], vh0[3]);
                mma16816(acc[mt][2], ah[mt], vh1[0], vh1[1]);
                mma16816(acc[mt][2], ah[mt], vl1[0], vl1[1]);
                mma16816(acc[mt][2], al[mt], vh1[0], vh1[1]);
                mma16816(acc[mt][3], ah[mt], vh1[2], vh1[3]);
                mma16816(acc[mt][3], ah[mt], vl1[2], vl1[3]);
                mma16816(acc[mt][3], al[mt], vh1[2], vh1[3]);
            }
        }
        if (c + 2 < nc) load_chunk(c + 2);
        CP_COMMIT();
    }

    // epilogue: split-store wa
    const int g = lane >> 2, tg = lane & 3;
    #pragma unroll
    for (int mt = 0; mt < 2; mt++) {
        #pragma unroll
        for (int nt = 0; nt < 4; nt++) {
            const int col = wn + nt * 8 + tg * 2;
            #pragma unroll
            for (int hh = 0; hh < 2; hh++) {
                const int row = q0 + wm + mt * 16 + g + hh * 8;
                if (row < T_) {
                    float v0 = acc[mt][nt][hh * 2];
                    float v1 = acc[mt][nt][hh * 2 + 1];
                    size_t go = ((size_t)(b * T_ + row)) * D_ + h * 64 + col;
                    __nv_bfloat162 h2, l2;
                    h2.x = __float2bfloat16(v0); h2.y = __float2bfloat16(v1);
                    l2.x = __float2bfloat16(v0 - __bfloat162float(h2.x));
                    l2.y = __float2bfloat16(v1 - __bfloat162float(h2.y));
                    *(__nv_bfloat162*)(whi + go) = h2;
                    *(__nv_bfloat162*)(wlo + go) = l2;
                }
            }
        }
    }
}

// ---------------- host launch ----------------
extern "C" void kernel_launch(void* const* d_in, const int* in_sizes, int n_in,
                              void* d_out, int out_size) {
    const float* x      = (const float*)d_in[0];
    const float* ln1_w  = (const float*)d_in[1];
    const float* ln1_b  = (const float*)d_in[2];
    const float* qkv_w  = (const float*)d_in[3];
    const float* qkv_b  = (const float*)d_in[4];
    const float* proj_w = (const float*)d_in[5];
    const float* proj_b = (const float*)d_in[6];
    const float* ln2_w  = (const float*)d_in[7];
    const float* ln2_b  = (const float*)d_in[8];
    const float* fc1_w  = (const float*)d_in[9];
    const float* fc1_b  = (const float*)d_in[10];
    const float* fc2_w  = (const float*)d_in[11];
    const float* fc2_b  = (const float*)d_in[12];
    float* out = (float*)d_out;

    __nv_bfloat16 *yhi, *ylo, *qkh, *qkl, *ph, *pl, *wahi, *walo, *hhi, *hlo;
    __nv_bfloat16 *wqh, *wql, *wph, *wpl, *w1h, *w1l, *w2h, *w2l;
    float *dpb, *x1b;
    cudaGetSymbolAddress((void**)&yhi,  g_y_hi);
    cudaGetSymbolAddress((void**)&ylo,  g_y_lo);
    cudaGetSymbolAddress((void**)&qkh,  g_qkv_hi);
    cudaGetSymbolAddress((void**)&qkl,  g_qkv_lo);
    cudaGetSymbolAddress((void**)&dpb,  g_dp);
    cudaGetSymbolAddress((void**)&ph,   g_p_hi);
    cudaGetSymbolAddress((void**)&pl,   g_p_lo);
    cudaGetSymbolAddress((void**)&wahi, g_wa_hi);
    cudaGetSymbolAddress((void**)&walo, g_wa_lo);
    cudaGetSymbolAddress((void**)&x1b,  g_x1);
    cudaGetSymbolAddress((void**)&hhi,  g_h_hi);
    cudaGetSymbolAddress((void**)&hlo,  g_h_lo);
    cudaGetSymbolAddress((void**)&wqh,  g_wq_hi);
    cudaGetSymbolAddress((void**)&wql,  g_wq_lo);
    cudaGetSymbolAddress((void**)&wph,  g_wp_hi);
    cudaGetSymbolAddress((void**)&wpl,  g_wp_lo);
    cudaGetSymbolAddress((void**)&w1h,  g_w1_hi);
    cudaGetSymbolAddress((void**)&w1l,  g_w1_lo);
    cudaGetSymbolAddress((void**)&w2h,  g_w2_hi);
    cudaGetSymbolAddress((void**)&w2l,  g_w2_lo);

    const int SMEM_G = 3 * 40960;          // 122880
    const int SMEM_W = 3 * (int)STGW;      // 89088
    cudaFuncSetAttribute(gemm_lin<0, false, true >, cudaFuncAttributeMaxDynamicSharedMemorySize, SMEM_G);
    cudaFuncSetAttribute(gemm_lin<0, true,  false>, cudaFuncAttributeMaxDynamicSharedMemorySize, SMEM_G);
    cudaFuncSetAttribute(gemm_lin<1, false, true >, cudaFuncAttributeMaxDynamicSharedMemorySize, SMEM_G);
    cudaFuncSetAttribute(scores_mma, cudaFuncAttributeMaxDynamicSharedMemorySize, SMEM_G);
    cudaFuncSetAttribute(wa_mma,     cudaFuncAttributeMaxDynamicSharedMemorySize, SMEM_W);

    const int MT = (BT + 127) / 128;  // 145

    wconv_kernel<<<dim3(2304 / 32, 768 / 32),  dim3(32, 8)>>>(qkv_w,  wqh, wql, 768,  2304);
    wconv_kernel<<<dim3(768 / 32,  768 / 32),  dim3(32, 8)>>>(proj_w, wph, wpl, 768,  768);
    wconv_kernel<<<dim3(3072 / 32, 768 / 32),  dim3(32, 8)>>>(fc1_w,  w1h, w1l, 768,  3072);
    wconv_kernel<<<dim3(768 / 32,  3072 / 32), dim3(32, 8)>>>(fc2_w,  w2h, w2l, 3072, 768);

    // 1) LN1 -> split
    ln_kernel<<<BT, 256>>>(x, ln1_w, ln1_b, yhi, ylo);
    // 2) QKV projection -> split bf16 qkv
    gemm_lin<0, false, true><<<dim3(2304 / 128, MT), 256, SMEM_G>>>(
        yhi, ylo, wqh, wql, qkv_b, nullptr, nullptr, qkh, qkl, BT, 2304, D_);
    // 3) scores (HMMA) -> fp32 dp (padded rows)
    scores_mma<<<dim3(5, 5, B_ * NH), 256, SMEM_G>>>(qkh, qkl, dpb);
    // 4) softmax over heads -> split bf16 probs
    {
        long long total = (long long)B_ * PTT;
        int grid = (int)((total + 255) / 256);
        softmax_split<<<grid, 256>>>(dpb, ph, pl);
    }
    // 5) wa = probs @ V (HMMA) -> split
    wa_mma<<<dim3(5, B_ * NH), 256, SMEM_W>>>(ph, pl, qkh, qkl, wahi, walo);
    // 6) output projection + residual
    gemm_lin<0, true, false><<<dim3(D_ / 128, MT), 256, SMEM_G>>>(
        wahi, walo, wph, wpl, proj_b, x, x1b, nullptr, nullptr, BT, D_, D_);
    // 7) LN2 -> split
    ln_kernel<<<BT, 256>>>(x1b, ln2_w, ln2_b, yhi, ylo);
    // 8) fc1 + exact GELU -> split
    gemm_lin<1, false, true><<<dim3(H_ / 128, MT), 256, SMEM_G>>>(
        yhi, ylo, w1h, w1l, fc1_b, nullptr, nullptr, hhi, hlo, BT, H_, D_);
    // 9) fc2 + residual -> output
    gemm_lin<0, true, false><<<dim3(D_ / 128, MT), 256, SMEM_G>>>(
        hhi, hlo, w2h, w2l, fc2_b, x1b, out, nullptr, nullptr, BT, D_, H_);
}

// round 6
// speedup vs baseline: 2.3251x; 1.0270x over previous
#include <cuda_runtime.h>
#include <cuda_bf16.h>
#include <math.h>
#include <stdint.h>

#define BT   18464          // B*T
#define B_   32
#define T_   577
#define D_   768
#define H_   3072
#define NH   12
#define KPAD 584            // padded key dim for dp/probs rows (16B-aligned)
#define PTT  (T_ * KPAD)    // per-(b,h) plane size (divisible by 4)

// ---------------- static scratch ----------------
__device__ __nv_bfloat16 g_y_hi [(size_t)BT * D_];
__device__ __nv_bfloat16 g_y_lo [(size_t)BT * D_];
__device__ __nv_bfloat16 g_qkv_hi[(size_t)BT * 2304];
__device__ __nv_bfloat16 g_qkv_lo[(size_t)BT * 2304];
__device__ float         g_dp   [(size_t)B_ * NH * PTT];
__device__ __nv_bfloat16 g_p_hi [(size_t)B_ * NH * PTT];
__device__ __nv_bfloat16 g_p_lo [(size_t)B_ * NH * PTT];
__device__ __nv_bfloat16 g_wa_hi[(size_t)BT * D_];
__device__ __nv_bfloat16 g_wa_lo[(size_t)BT * D_];
__device__ float         g_x1   [(size_t)BT * D_];
__device__ __nv_bfloat16 g_h_hi [(size_t)BT * H_];
__device__ __nv_bfloat16 g_h_lo [(size_t)BT * H_];
__device__ __nv_bfloat16 g_wq_hi[2304 * 768], g_wq_lo[2304 * 768];
__device__ __nv_bfloat16 g_wp_hi[ 768 * 768], g_wp_lo[ 768 * 768];
__device__ __nv_bfloat16 g_w1_hi[3072 * 768], g_w1_lo[3072 * 768];
__device__ __nv_bfloat16 g_w2_hi[ 768 * 3072], g_w2_lo[ 768 * 3072];

// ---------------- helpers ----------------
__device__ __forceinline__ uint32_t smem_u32(const void* p) {
    uint32_t a;
    asm("{ .reg .u64 t; cvta.to.shared.u64 t, %1; cvt.u32.u64 %0, t; }" : "=r"(a) : "l"(p));
    return a;
}
__device__ __forceinline__ void cp16(uint32_t dst, const void* src) {
    asm volatile("cp.async.cg.shared.global [%0], [%1], 16;" :: "r"(dst), "l"(src));
}
__device__ __forceinline__ void cp16z(uint32_t dst, const void* src, int nb) {
    asm volatile("cp.async.cg.shared.global [%0], [%1], 16, %2;" :: "r"(dst), "l"(src), "r"(nb));
}
#define CP_COMMIT() asm volatile("cp.async.commit_group;" ::: "memory")
#define CP_WAIT(n)  asm volatile("cp.async.wait_group %0;" :: "n"(n) : "memory")

__device__ __forceinline__ void ldsm4(uint32_t* r, uint32_t a) {
    asm volatile("ldmatrix.sync.aligned.m8n8.x4.shared.b16 {%0,%1,%2,%3}, [%4];"
                 : "=r"(r[0]), "=r"(r[1]), "=r"(r[2]), "=r"(r[3]) : "r"(a));
}
__device__ __forceinline__ void ldsm4t(uint32_t* r, uint32_t a) {
    asm volatile("ldmatrix.sync.aligned.m8n8.x4.trans.shared.b16 {%0,%1,%2,%3}, [%4];"
                 : "=r"(r[0]), "=r"(r[1]), "=r"(r[2]), "=r"(r[3]) : "r"(a));
}
__device__ __forceinline__ void mma16816(float* c, const uint32_t* a, uint32_t b0, uint32_t b1) {
    asm volatile("mma.sync.aligned.m16n8k16.row.col.f32.bf16.bf16.f32 "
                 "{%0,%1,%2,%3}, {%4,%5,%6,%7}, {%8,%9}, {%0,%1,%2,%3};"
                 : "+f"(c[0]), "+f"(c[1]), "+f"(c[2]), "+f"(c[3])
                 : "r"(a[0]), "r"(a[1]), "r"(a[2]), "r"(a[3]), "r"(b0), "r"(b1));
}

// ---------------- weight transpose+split ----------------
__global__ void wconv_kernel(const float* __restrict__ W,
                             __nv_bfloat16* __restrict__ hi,
                             __nv_bfloat16* __restrict__ lo, int K, int N) {
    __shared__ float t[32][33];
    const int k0 = blockIdx.y * 32, n0 = blockIdx.x * 32;
    #pragma unroll
    for (int i = 0; i < 4; i++)
        t[threadIdx.y + i * 8][threadIdx.x] =
            W[(size_t)(k0 + threadIdx.y + i * 8) * N + n0 + threadIdx.x];
    __syncthreads();
    #pragma unroll
    for (int i = 0; i < 4; i++) {
        int n = n0 + threadIdx.y + i * 8;
        int k = k0 + threadIdx.x;
        float x = t[threadIdx.x][threadIdx.y + i * 8];
        __nv_bfloat16 h = __float2bfloat16(x);
        hi[(size_t)n * K + k] = h;
        lo[(size_t)n * K + k] = __float2bfloat16(x - __bfloat162float(h));
    }
}

// ---------------- LayerNorm -> split bf16 ----------------
__global__ void __launch_bounds__(256) ln_kernel(const float* __restrict__ x,
                                                 const float* __restrict__ w,
                                                 const float* __restrict__ b,
                                                 __nv_bfloat16* __restrict__ yhi,
                                                 __nv_bfloat16* __restrict__ ylo) {
    const int row = blockIdx.x;
    const float* xr = x + (size_t)row * D_;
    const int tid = threadIdx.x;

    float v0 = xr[tid], v1 = xr[tid + 256], v2 = xr[tid + 512];
    float s  = v0 + v1 + v2;
    float s2 = v0 * v0 + v1 * v1 + v2 * v2;
    #pragma unroll
    for (int o = 16; o > 0; o >>= 1) {
        s  += __shfl_xor_sync(0xffffffffu, s,  o);
        s2 += __shfl_xor_sync(0xffffffffu, s2, o);
    }
    __shared__ float sh[8], sh2[8];
    const int wi = tid >> 5, ln = tid & 31;
    if (ln == 0) { sh[wi] = s; sh2[wi] = s2; }
    __syncthreads();
    if (wi == 0) {
        s  = (ln < 8) ? sh[ln]  : 0.f;
        s2 = (ln < 8) ? sh2[ln] : 0.f;
        #pragma unroll
        for (int o = 4; o > 0; o >>= 1) {
            s  += __shfl_xor_sync(0xffffffffu, s,  o);
            s2 += __shfl_xor_sync(0xffffffffu, s2, o);
        }
        if (ln == 0) { sh[0] = s; sh2[0] = s2; }
    }
    __syncthreads();
    const float mu  = sh[0] * (1.0f / D_);
    const float var = sh2[0] * (1.0f / D_) - mu * mu;
    const float rs  = rsqrtf(var + 1e-6f);
    size_t base = (size_t)row * D_;
    #pragma unroll
    for (int j = 0; j < 3; j++) {
        int c = tid + j * 256;
        float v = (j == 0 ? v0 : (j == 1 ? v1 : v2));
        float y = (v - mu) * rs * w[c] + b[c];
        __nv_bfloat16 h = __float2bfloat16(y);
        yhi[base + c] = h;
        ylo[base + c] = __float2bfloat16(y - __bfloat162float(h));
    }
}

// ================= linear GEMM: 128x256 CTA, 8 warps of 64x64, BK=32, 3-stage =================
// stage: Ahi@0 (128x80B), Alo@10240, Bhi@20480 (256x80B), Blo@40960; stage=61440
#define STG2 61440u
template <int ACT, bool RES, bool OSPLIT>
__global__ void __launch_bounds__(256, 1) gemm_lin(
    const __nv_bfloat16* __restrict__ Ahi, const __nv_bfloat16* __restrict__ Alo,
    const __nv_bfloat16* __restrict__ Whi, const __nv_bfloat16* __restrict__ Wlo,
    const float* __restrict__ bias, const float* __restrict__ res,
    float* __restrict__ C, __nv_bfloat16* __restrict__ Chi, __nv_bfloat16* __restrict__ Clo,
    int M, int N, int K) {
    extern __shared__ char dsm[];
    const uint32_t sb = smem_u32(dsm);
    const int tid = threadIdx.x;
    const int lane = tid & 31, wid = tid >> 5;
    const int m0 = blockIdx.y * 128, n0 = blockIdx.x * 256;
    const int wm = (wid & 1) * 64, wn = (wid >> 1) * 64;
    const int lrow = tid >> 2;
    const int lq   = (tid & 3) * 16;
    const int mi = lane >> 3, r8 = lane & 7;
    const uint32_t aoff = (uint32_t)((wm + (mi & 1) * 8 + r8) * 80 + ((mi >> 1) * 8) * 2);
    const uint32_t boff = (uint32_t)((wn + (mi >> 1) * 8 + r8) * 80 + ((mi & 1) * 8) * 2);

    float acc[4][8][4];
    #pragma unroll
    for (int a = 0; a < 4; a++)
        #pragma unroll
        for (int b = 0; b < 8; b++)
            #pragma unroll
            for (int d = 0; d < 4; d++) acc[a][b][d] = 0.f;

    const int nc = K >> 5;

    auto load_chunk = [&](int c) {
        const uint32_t st = sb + (uint32_t)(c % 3) * STG2;
        const int k0 = c << 5;
        #pragma unroll
        for (int i = 0; i < 2; i++) {       // A: 128 rows
            int r = lrow + i * 64;
            int gr = m0 + r; if (gr > M - 1) gr = M - 1;
            uint32_t d = st + (uint32_t)(r * 80) + lq;
            cp16(d,          (const char*)(Ahi + (size_t)gr * K + k0) + lq);
            cp16(d + 10240u, (const char*)(Alo + (size_t)gr * K + k0) + lq);
        }
        #pragma unroll
        for (int i = 0; i < 4; i++) {       // B: 256 rows (N%256==0)
            int r = lrow + i * 64;
            size_t gb = (size_t)(n0 + r) * K + k0;
            uint32_t d = st + 20480u + (uint32_t)(r * 80) + lq;
            cp16(d,          (const char*)(Whi + gb) + lq);
            cp16(d + 20480u, (const char*)(Wlo + gb) + lq);
        }
    };

    load_chunk(0); CP_COMMIT();
    if (nc > 1) load_chunk(1);
    CP_COMMIT();

    for (int c = 0; c < nc; c++) {
        CP_WAIT(1);
        __syncthreads();
        const uint32_t st = sb + (uint32_t)(c % 3) * STG2;
        #pragma unroll
        for (int kb = 0; kb < 2; kb++) {
            const uint32_t ko = (uint32_t)(kb * 32);
            uint32_t ah[4][4], al[4][4];
            #pragma unroll
            for (int mt = 0; mt < 4; mt++) {
                ldsm4(ah[mt], st + aoff + (uint32_t)(mt * 1280) + ko);
                ldsm4(al[mt], st + 10240u + aoff + (uint32_t)(mt * 1280) + ko);
            }
            #pragma unroll
            for (int p = 0; p < 4; p++) {
                uint32_t bh[4], bl[4];
                ldsm4(bh, st + 20480u + boff + (uint32_t)(p * 1280) + ko);
                ldsm4(bl, st + 40960u + boff + (uint32_t)(p * 1280) + ko);
                #pragma unroll
                for (int mt = 0; mt < 4; mt++) {
                    mma16816(acc[mt][2 * p],     ah[mt], bh[0], bh[1]);
                    mma16816(acc[mt][2 * p],     ah[mt], bl[0], bl[1]);
                    mma16816(acc[mt][2 * p],     al[mt], bh[0], bh[1]);
                    mma16816(acc[mt][2 * p + 1], ah[mt], bh[2], bh[3]);
                    mma16816(acc[mt][2 * p + 1], ah[mt], bl[2], bl[3]);
                    mma16816(acc[mt][2 * p + 1], al[mt], bh[2], bh[3]);
                }
            }
        }
        if (c + 2 < nc) load_chunk(c + 2);
        CP_COMMIT();
    }

    // epilogue
    const int g = lane >> 2, tg = lane & 3;
    #pragma unroll
    for (int mt = 0; mt < 4; mt++) {
        const int rb = m0 + wm + mt * 16 + g;
        #pragma unroll
        for (int nt = 0; nt < 8; nt++) {
            const int col = n0 + wn + nt * 8 + tg * 2;
            const float bv0 = bias[col], bv1 = bias[col + 1];
            #pragma unroll
            for (int hh = 0; hh < 2; hh++) {
                const int row = rb + hh * 8;
                if (row < M) {
                    float v0 = acc[mt][nt][hh * 2]     + bv0;
                    float v1 = acc[mt][nt][hh * 2 + 1] + bv1;
                    if (ACT == 1) { v0 = v0 * normcdff(v0); v1 = v1 * normcdff(v1); }
                    size_t go = (size_t)row * N + col;
                    if (RES) {
                        float2 r2 = *(const float2*)(res + go);
                        v0 += r2.x; v1 += r2.y;
                    }
                    if (OSPLIT) {
                        __nv_bfloat162 h2, l2;
                        h2.x = __float2bfloat16(v0); h2.y = __float2bfloat16(v1);
                        l2.x = __float2bfloat16(v0 - __bfloat162float(h2.x));
                        l2.y = __float2bfloat16(v1 - __bfloat162float(h2.y));
                        *(__nv_bfloat162*)(Chi + go) = h2;
                        *(__nv_bfloat162*)(Clo + go) = l2;
                    } else {
                        *(float2*)(C + go) = make_float2(v0, v1);
                    }
                }
            }
        }
    }
}

// ================= scores: 128x128 tile, K=64 in two preloaded chunks =================
#define STG 40960u
__global__ void __launch_bounds__(256, 1) scores_mma(
    const __nv_bfloat16* __restrict__ qkvh, const __nv_bfloat16* __restrict__ qkvl,
    float* __restrict__ dp) {
    extern __shared__ char dsm[];
    const uint32_t sb = smem_u32(dsm);
    const int bh = blockIdx.z;
    const int bb = bh / NH, h = bh % NH;
    const size_t qb = (size_t)bb * T_ * 2304 + h * 64;
    const size_t kb_ = qb + 768;
    float* Cp = dp + (size_t)bh * PTT;
    const int m0 = blockIdx.y * 128, n0 = blockIdx.x * 128;

    const int tid = threadIdx.x;
    const int lane = tid & 31, wid = tid >> 5;
    const int wm = (wid & 3) * 32, wn = (wid >> 2) * 64;
    const int lrow = tid >> 2;
    const int lq   = (tid & 3) * 16;
    const int mi = lane >> 3, r8 = lane & 7;
    const uint32_t aoff = (uint32_t)((wm + (mi & 1) * 8 + r8) * 80 + ((mi >> 1) * 8) * 2);
    const uint32_t boff = (uint32_t)((wn + (mi >> 1) * 8 + r8) * 80 + ((mi & 1) * 8) * 2);

    float acc[2][8][4];
    #pragma unroll
    for (int a = 0; a < 2; a++)
        #pragma unroll
        for (int b = 0; b < 8; b++)
            #pragma unroll
            for (int d = 0; d < 4; d++) acc[a][b][d] = 0.f;

    auto load_chunk = [&](int c) {
        const uint32_t st = sb + (uint32_t)c * STG;
        const int k0 = c << 5;
        #pragma unroll
        for (int i = 0; i < 2; i++) {
            int r = lrow + i * 64;
            int gq = m0 + r; if (gq > T_ - 1) gq = T_ - 1;
            int gk = n0 + r; if (gk > T_ - 1) gk = T_ - 1;
            uint32_t d = st + (uint32_t)(r * 80) + lq;
            cp16(d,          (const char*)(qkvh + qb  + (size_t)gq * 2304 + k0) + lq);
            cp16(d + 10240u, (const char*)(qkvl + qb  + (size_t)gq * 2304 + k0) + lq);
            cp16(d + 20480u, (const char*)(qkvh + kb_ + (size_t)gk * 2304 + k0) + lq);
            cp16(d + 30720u, (const char*)(qkvl + kb_ + (size_t)gk * 2304 + k0) + lq);
        }
    };

    load_chunk(0); CP_COMMIT();
    load_chunk(1); CP_COMMIT();

    #pragma unroll
    for (int c = 0; c < 2; c++) {
        if (c == 0) { CP_WAIT(1); }   // group 0 complete
        else        { CP_WAIT(0); }   // ALL groups complete (fixes round-5 race)
        __syncthreads();
        const uint32_t st = sb + (uint32_t)c * STG;
        #pragma unroll
        for (int kb = 0; kb < 2; kb++) {
            const uint32_t ko = (uint32_t)(kb * 32);
            uint32_t ah[2][4], al[2][4];
            ldsm4(ah[0], st + aoff + ko);
            ldsm4(ah[1], st + aoff + 1280u + ko);
            ldsm4(al[0], st + 10240u + aoff + ko);
            ldsm4(al[1], st + 10240u + aoff + 1280u + ko);
            #pragma unroll
            for (int p = 0; p < 4; p++) {
                uint32_t bh[4], bl[4];
                ldsm4(bh, st + 20480u + boff + (uint32_t)(p * 1280) + ko);
                ldsm4(bl, st + 30720u + boff + (uint32_t)(p * 1280) + ko);
                #pragma unroll
                for (int mt = 0; mt < 2; mt++) {
                    mma16816(acc[mt][2 * p],     ah[mt], bh[0], bh[1]);
                    mma16816(acc[mt][2 * p],     ah[mt], bl[0], bl[1]);
                    mma16816(acc[mt][2 * p],     al[mt], bh[0], bh[1]);
                    mma16816(acc[mt][2 * p + 1], ah[mt], bh[2], bh[3]);
                    mma16816(acc[mt][2 * p + 1], ah[mt], bl[2], bl[3]);
                    mma16816(acc[mt][2 * p + 1], al[mt], bh[2], bh[3]);
                }
            }
        }
    }

    const int g = lane >> 2, tg = lane & 3;
    #pragma unroll
    for (int mt = 0; mt < 2; mt++) {
        const int rb = m0 + wm + mt * 16 + g;
        #pragma unroll
        for (int nt = 0; nt < 8; nt++) {
            const int col = n0 + wn + nt * 8 + tg * 2;
            #pragma unroll
            for (int hh = 0; hh < 2; hh++) {
                const int row = rb + hh * 8;
                if (row < T_ && col < T_) {
                    float v0 = acc[mt][nt][hh * 2]     * 0.125f;
                    float v1 = acc[mt][nt][hh * 2 + 1] * 0.125f;
                    size_t go = (size_t)row * KPAD + col;
                    if (col + 1 < T_) *(float2*)(Cp + go) = make_float2(v0, v1);
                    else Cp[go] = v0;
                }
            }
        }
    }
}

// ---------------- softmax over HEADS -> split bf16 probs (x4 vectorized) ----------------
__global__ void softmax_split(const float* __restrict__ dp,
                              __nv_bfloat16* __restrict__ phi,
                              __nv_bfloat16* __restrict__ plo) {
    long long idx = (long long)blockIdx.x * blockDim.x + threadIdx.x;
    const long long tot = (long long)B_ * (PTT / 4);
    if (idx >= tot) return;
    const int b  = (int)(idx / (PTT / 4));
    const int r4 = (int)(idx % (PTT / 4));
    size_t base = (size_t)b * NH * PTT + (size_t)r4 * 4;
    float4 v[NH];
    float4 mx = make_float4(-1e30f, -1e30f, -1e30f, -1e30f);
    #pragma unroll
    for (int h = 0; h < NH; h++) {
        v[h] = *(const float4*)(dp + base + (size_t)h * PTT);
        mx.x = fmaxf(mx.x, v[h].x); mx.y = fmaxf(mx.y, v[h].y);
        mx.z = fmaxf(mx.z, v[h].z); mx.w = fmaxf(mx.w, v[h].w);
    }
    float4 s = make_float4(0.f, 0.f, 0.f, 0.f);
    #pragma unroll
    for (int h = 0; h < NH; h++) {
        v[h].x = expf(v[h].x - mx.x); s.x += v[h].x;
        v[h].y = expf(v[h].y - mx.y); s.y += v[h].y;
        v[h].z = expf(v[h].z - mx.z); s.z += v[h].z;
        v[h].w = expf(v[h].w - mx.w); s.w += v[h].w;
    }
    s.x = 1.f / s.x; s.y = 1.f / s.y; s.z = 1.f / s.z; s.w = 1.f / s.w;
    #pragma unroll
    for (int h = 0; h < NH; h++) {
        float p0 = v[h].x * s.x, p1 = v[h].y * s.y, p2 = v[h].z * s.z, p3 = v[h].w * s.w;
        __nv_bfloat162 h0, h1, l0, l1;
        h0.x = __float2bfloat16(p0); h0.y = __float2bfloat16(p1);
        h1.x = __float2bfloat16(p2); h1.y = __float2bfloat16(p3);
        l0.x = __float2bfloat16(p0 - __bfloat162float(h0.x));
        l0.y = __float2bfloat16(p1 - __bfloat162float(h0.y));
        l1.x = __float2bfloat16(p2 - __bfloat162float(h1.x));
        l1.y = __float2bfloat16(p3 - __bfloat162float(h1.y));
        size_t o = base + (size_t)h * PTT;
        *(__nv_bfloat162*)(phi + o)     = h0;
        *(__nv_bfloat162*)(phi + o + 2) = h1;
        *(__nv_bfloat162*)(plo + o)     = l0;
        *(__nv_bfloat162*)(plo + o + 2) = l1;
    }
}

// ---------------- wa = probs @ V (HMMA, ldmatrix.trans for V) ----------------
#define STGW 29696u
__global__ void __launch_bounds__(256, 1) wa_mma(
    const __nv_bfloat16* __restrict__ phi, const __nv_bfloat16* __restrict__ plo,
    const __nv_bfloat16* __restrict__ qkvh, const __nv_bfloat16* __restrict__ qkvl,
    __nv_bfloat16* __restrict__ whi, __nv_bfloat16* __restrict__ wlo) {
    extern __shared__ char dsm[];
    const uint32_t sb = smem_u32(dsm);
    const int tid = threadIdx.x;
    const int lane = tid & 31, wid = tid >> 5;
    const int bh = blockIdx.y;
    const int b = bh / NH, h = bh % NH;
    const int q0 = blockIdx.x * 128;
    const int wm = (wid & 3) * 32, wn = (wid >> 2) * 32;
    const int lrow = tid >> 2;
    const int lq   = (tid & 3) * 16;
    const int mi = lane >> 3, r8 = lane & 7;
    const uint32_t aoff = (uint32_t)((wm + (mi & 1) * 8 + r8) * 80 + ((mi >> 1) * 8) * 2);
    const uint32_t voff = (uint32_t)(((mi & 1) * 8 + r8) * 144 + (wn + (mi >> 1) * 8) * 2);

    const size_t pbase = (size_t)bh * PTT;
    const size_t vbase = (size_t)b * T_ * 2304 + 1536 + h * 64;

    float acc[2][4][4];
    #pragma unroll
    for (int a = 0; a < 2; a++)
        #pragma unroll
        for (int n = 0; n < 4; n++)
            #pragma unroll
            for (int d = 0; d < 4; d++) acc[a][n][d] = 0.f;

    const int nc = (T_ + 31) / 32;  // 19

    auto load_chunk = [&](int c) {
        const uint32_t st = sb + (uint32_t)(c % 3) * STGW;
        const int k0 = c * 32;
        #pragma unroll
        for (int i = 0; i < 2; i++) {
            int r = lrow + i * 64;
            int q = q0 + r; if (q > T_ - 1) q = T_ - 1;
            int kstart = k0 + (lq >> 1);
            int nb = (T_ - kstart) * 2;
            nb = nb < 0 ? 0 : (nb > 16 ? 16 : nb);
            size_t off = pbase + (size_t)q * KPAD + k0;
            uint32_t d = st + (uint32_t)(r * 80) + lq;
            cp16z(d,          (const char*)(phi + off) + lq, nb);
            cp16z(d + 10240u, (const char*)(plo + off) + lq, nb);
        }
        {
            int vr = tid >> 3, vq = (tid & 7) * 16;
            int k = k0 + vr;
            int nb = (k < T_) ? 16 : 0;
            if (k > T_ - 1) k = T_ - 1;
            size_t off = vbase + (size_t)k * 2304;
            uint32_t d = st + 20480u + (uint32_t)(vr * 144) + vq;
            cp16z(d,         (const char*)(qkvh + off) + vq, nb);
            cp16z(d + 4608u, (const char*)(qkvl + off) + vq, nb);
        }
    };

    load_chunk(0); CP_COMMIT();
    load_chunk(1); CP_COMMIT();

    for (int c = 0; c < nc; c++) {
        CP_WAIT(1);
        __syncthreads();
        const uint32_t st = sb + (uint32_t)(c % 3) * STGW;
        #pragma unroll
        for (int ks = 0; ks < 2; ks++) {
            const uint32_t ko = (uint32_t)(ks * 32);
            uint32_t ah[2][4], al[2][4];
            ldsm4(ah[0], st + aoff + ko);
            ldsm4(ah[1], st + aoff + 1280u + ko);
            ldsm4(al[0], st + 10240u + aoff + ko);
            ldsm4(al[1], st + 10240u + aoff + 1280u + ko);
            uint32_t vh0[4], vh1[4], vl0[4], vl1[4];
            const uint32_t vb = st + 20480u + voff + (uint32_t)(ks * 2304);
            ldsm4t(vh0, vb);
            ldsm4t(vh1, vb + 32u);
            ldsm4t(vl0, vb + 4608u);
            ldsm4t(vl1, vb + 4608u + 32u);
            #pragma unroll
            for (int mt = 0; mt < 2; mt++) {
                mma16816(acc[mt][0], ah[mt], vh0[0], vh0[1]);
                mma16816(acc[mt][0], ah[mt], vl0[0], vl0[1]);
                mma16816(acc[mt][0], al[mt], vh0[0], vh0[1]);
                mma16816(acc[mt][1], ah[mt], vh0[2], vh0[3]);
                mma16816(acc[mt][1], ah[mt], vl0[2], vl0[3]);
                mma16816(acc[mt][1], al[mt], vh0[2], vh0[3]);
                mma16816(acc[mt][2], ah[mt], vh1[0], vh1[1]);
                mma16816(acc[mt][2], ah[mt], vl1[0], vl1[1]);
                mma16816(acc[mt][2], al[mt], vh1[0], vh1[1]);
                mma16816(acc[mt][3], ah[mt], vh1[2], vh1[3]);
                mma16816(acc[mt][3], ah[mt], vl1[2], vl1[3]);
                mma16816(acc[mt][3], al[mt], vh1[2], vh1[3]);
            }
        }
        if (c + 2 < nc) load_chunk(c + 2);
        CP_COMMIT();
    }

    const int g = lane >> 2, tg = lane & 3;
    #pragma unroll
    for (int mt = 0; mt < 2; mt++) {
        #pragma unroll
        for (int nt = 0; nt < 4; nt++) {
            const int col = wn + nt * 8 + tg * 2;
            #pragma unroll
            for (int hh = 0; hh < 2; hh++) {
                const int row = q0 + wm + mt * 16 + g + hh * 8;
                if (row < T_) {
                    float v0 = acc[mt][nt][hh * 2];
                    float v1 = acc[mt][nt][hh * 2 + 1];
                    size_t go = ((size_t)(b * T_ + row)) * D_ + h * 64 + col;
                    __nv_bfloat162 h2, l2;
                    h2.x = __float2bfloat16(v0); h2.y = __float2bfloat16(v1);
                    l2.x = __float2bfloat16(v0 - __bfloat162float(h2.x));
                    l2.y = __float2bfloat16(v1 - __bfloat162float(h2.y));
                    *(__nv_bfloat162*)(whi + go) = h2;
                    *(__nv_bfloat162*)(wlo + go) = l2;
                }
            }
        }
    }
}

// ---------------- host launch ----------------
extern "C" void kernel_launch(void* const* d_in, const int* in_sizes, int n_in,
                              void* d_out, int out_size) {
    const float* x      = (const float*)d_in[0];
    const float* ln1_w  = (const float*)d_in[1];
    const float* ln1_b  = (const float*)d_in[2];
    const float* qkv_w  = (const float*)d_in[3];
    const float* qkv_b  = (const float*)d_in[4];
    const float* proj_w = (const float*)d_in[5];
    const float* proj_b = (const float*)d_in[6];
    const float* ln2_w  = (const float*)d_in[7];
    const float* ln2_b  = (const float*)d_in[8];
    const float* fc1_w  = (const float*)d_in[9];
    const float* fc1_b  = (const float*)d_in[10];
    const float* fc2_w  = (const float*)d_in[11];
    const float* fc2_b  = (const float*)d_in[12];
    float* out = (float*)d_out;

    __nv_bfloat16 *yhi, *ylo, *qkh, *qkl, *ph, *pl, *wahi, *walo, *hhi, *hlo;
    __nv_bfloat16 *wqh, *wql, *wph, *wpl, *w1h, *w1l, *w2h, *w2l;
    float *dpb, *x1b;
    cudaGetSymbolAddress((void**)&yhi,  g_y_hi);
    cudaGetSymbolAddress((void**)&ylo,  g_y_lo);
    cudaGetSymbolAddress((void**)&qkh,  g_qkv_hi);
    cudaGetSymbolAddress((void**)&qkl,  g_qkv_lo);
    cudaGetSymbolAddress((void**)&dpb,  g_dp);
    cudaGetSymbolAddress((void**)&ph,   g_p_hi);
    cudaGetSymbolAddress((void**)&pl,   g_p_lo);
    cudaGetSymbolAddress((void**)&wahi, g_wa_hi);
    cudaGetSymbolAddress((void**)&walo, g_wa_lo);
    cudaGetSymbolAddress((void**)&x1b,  g_x1);
    cudaGetSymbolAddress((void**)&hhi,  g_h_hi);
    cudaGetSymbolAddress((void**)&hlo,  g_h_lo);
    cudaGetSymbolAddress((void**)&wqh,  g_wq_hi);
    cudaGetSymbolAddress((void**)&wql,  g_wq_lo);
    cudaGetSymbolAddress((void**)&wph,  g_wp_hi);
    cudaGetSymbolAddress((void**)&wpl,  g_wp_lo);
    cudaGetSymbolAddress((void**)&w1h,  g_w1_hi);
    cudaGetSymbolAddress((void**)&w1l,  g_w1_lo);
    cudaGetSymbolAddress((void**)&w2h,  g_w2_hi);
    cudaGetSymbolAddress((void**)&w2l,  g_w2_lo);

    const int SMEM_L = 3 * (int)STG2;      // 184320
    const int SMEM_S = 2 * (int)STG;       // 81920
    const int SMEM_W = 3 * (int)STGW;      // 89088
    cudaFuncSetAttribute(gemm_lin<0, false, true >, cudaFuncAttributeMaxDynamicSharedMemorySize, SMEM_L);
    cudaFuncSetAttribute(gemm_lin<0, true,  false>, cudaFuncAttributeMaxDynamicSharedMemorySize, SMEM_L);
    cudaFuncSetAttribute(gemm_lin<1, false, true >, cudaFuncAttributeMaxDynamicSharedMemorySize, SMEM_L);
    cudaFuncSetAttribute(scores_mma, cudaFuncAttributeMaxDynamicSharedMemorySize, SMEM_S);
    cudaFuncSetAttribute(wa_mma,     cudaFuncAttributeMaxDynamicSharedMemorySize, SMEM_W);

    const int MT = (BT + 127) / 128;  // 145

    wconv_kernel<<<dim3(2304 / 32, 768 / 32),  dim3(32, 8)>>>(qkv_w,  wqh, wql, 768,  2304);
    wconv_kernel<<<dim3(768 / 32,  768 / 32),  dim3(32, 8)>>>(proj_w, wph, wpl, 768,  768);
    wconv_kernel<<<dim3(3072 / 32, 768 / 32),  dim3(32, 8)>>>(fc1_w,  w1h, w1l, 768,  3072);
    wconv_kernel<<<dim3(768 / 32,  3072 / 32), dim3(32, 8)>>>(fc2_w,  w2h, w2l, 3072, 768);

    // 1) LN1 -> split
    ln_kernel<<<BT, 256>>>(x, ln1_w, ln1_b, yhi, ylo);
    // 2) QKV projection -> split bf16 qkv
    gemm_lin<0, false, true><<<dim3(2304 / 256, MT), 256, SMEM_L>>>(
        yhi, ylo, wqh, wql, qkv_b, nullptr, nullptr, qkh, qkl, BT, 2304, D_);
    // 3) scores -> fp32 dp (padded rows)
    scores_mma<<<dim3(5, 5, B_ * NH), 256, SMEM_S>>>(qkh, qkl, dpb);
    // 4) softmax over heads -> split bf16 probs
    {
        long long total = (long long)B_ * (PTT / 4);
        int grid = (int)((total + 255) / 256);
        softmax_split<<<grid, 256>>>(dpb, ph, pl);
    }
    // 5) wa = probs @ V -> split
    wa_mma<<<dim3(5, B_ * NH), 256, SMEM_W>>>(ph, pl, qkh, qkl, wahi, walo);
    // 6) output projection + residual
    gemm_lin<0, true, false><<<dim3(D_ / 256, MT), 256, SMEM_L>>>(
        wahi, walo, wph, wpl, proj_b, x, x1b, nullptr, nullptr, BT, D_, D_);
    // 7) LN2 -> split
    ln_kernel<<<BT, 256>>>(x1b, ln2_w, ln2_b, yhi, ylo);
    // 8) fc1 + exact GELU -> split
    gemm_lin<1, false, true><<<dim3(H_ / 256, MT), 256, SMEM_L>>>(
        yhi, ylo, w1h, w1l, fc1_b, nullptr, nullptr, hhi, hlo, BT, H_, D_);
    // 9) fc2 + residual -> output
    gemm_lin<0, true, false><<<dim3(D_ / 256, MT), 256, SMEM_L>>>(
        hhi, hlo, w2h, w2l, fc2_b, x1b, out, nullptr, nullptr, BT, D_, H_);
}

// round 7
// speedup vs baseline: 2.5701x; 1.1054x over previous
#include <cuda_runtime.h>
#include <cuda_bf16.h>
#include <math.h>
#include <stdint.h>

#define BT   18464          // B*T
#define B_   32
#define T_   577
#define D_   768
#define H_   3072
#define NH   12
#define KPAD 584            // padded key dim for dp/probs rows (16B-aligned)
#define PTT  (T_ * KPAD)    // per-(b,h) plane size (divisible by 4)

// ---------------- static scratch ----------------
__device__ __nv_bfloat16 g_y_hi [(size_t)BT * D_];
__device__ __nv_bfloat16 g_y_lo [(size_t)BT * D_];
__device__ __nv_bfloat16 g_qkv_hi[(size_t)BT * 2304];
__device__ __nv_bfloat16 g_qkv_lo[(size_t)BT * 2304];
__device__ float         g_dp   [(size_t)B_ * NH * PTT];
__device__ __nv_bfloat16 g_p_hi [(size_t)B_ * NH * PTT];
__device__ __nv_bfloat16 g_p_lo [(size_t)B_ * NH * PTT];
__device__ __nv_bfloat16 g_wa_hi[(size_t)BT * D_];
__device__ __nv_bfloat16 g_wa_lo[(size_t)BT * D_];
__device__ float         g_x1   [(size_t)BT * D_];
__device__ __nv_bfloat16 g_h_hi [(size_t)BT * H_];
__device__ __nv_bfloat16 g_h_lo [(size_t)BT * H_];
__device__ __nv_bfloat16 g_wq_hi[2304 * 768], g_wq_lo[2304 * 768];
__device__ __nv_bfloat16 g_wp_hi[ 768 * 768], g_wp_lo[ 768 * 768];
__device__ __nv_bfloat16 g_w1_hi[3072 * 768], g_w1_lo[3072 * 768];
__device__ __nv_bfloat16 g_w2_hi[ 768 * 3072], g_w2_lo[ 768 * 3072];

// ---------------- helpers ----------------
__device__ __forceinline__ uint32_t smem_u32(const void* p) {
    uint32_t a;
    asm("{ .reg .u64 t; cvta.to.shared.u64 t, %1; cvt.u32.u64 %0, t; }" : "=r"(a) : "l"(p));
    return a;
}
__device__ __forceinline__ void cp16(uint32_t dst, const void* src) {
    asm volatile("cp.async.cg.shared.global [%0], [%1], 16;" :: "r"(dst), "l"(src));
}
__device__ __forceinline__ void cp16z(uint32_t dst, const void* src, int nb) {
    asm volatile("cp.async.cg.shared.global [%0], [%1], 16, %2;" :: "r"(dst), "l"(src), "r"(nb));
}
#define CP_COMMIT() asm volatile("cp.async.commit_group;" ::: "memory")
#define CP_WAIT(n)  asm volatile("cp.async.wait_group %0;" :: "n"(n) : "memory")

__device__ __forceinline__ void ldsm4(uint32_t* r, uint32_t a) {
    asm volatile("ldmatrix.sync.aligned.m8n8.x4.shared.b16 {%0,%1,%2,%3}, [%4];"
                 : "=r"(r[0]), "=r"(r[1]), "=r"(r[2]), "=r"(r[3]) : "r"(a));
}
__device__ __forceinline__ void ldsm4t(uint32_t* r, uint32_t a) {
    asm volatile("ldmatrix.sync.aligned.m8n8.x4.trans.shared.b16 {%0,%1,%2,%3}, [%4];"
                 : "=r"(r[0]), "=r"(r[1]), "=r"(r[2]), "=r"(r[3]) : "r"(a));
}
__device__ __forceinline__ void mma16816(float* c, const uint32_t* a, uint32_t b0, uint32_t b1) {
    asm volatile("mma.sync.aligned.m16n8k16.row.col.f32.bf16.bf16.f32 "
                 "{%0,%1,%2,%3}, {%4,%5,%6,%7}, {%8,%9}, {%0,%1,%2,%3};"
                 : "+f"(c[0]), "+f"(c[1]), "+f"(c[2]), "+f"(c[3])
                 : "r"(a[0]), "r"(a[1]), "r"(a[2]), "r"(a[3]), "r"(b0), "r"(b1));
}

// ---------------- weight transpose+split ----------------
__global__ void wconv_kernel(const float* __restrict__ W,
                             __nv_bfloat16* __restrict__ hi,
                             __nv_bfloat16* __restrict__ lo, int K, int N) {
    __shared__ float t[32][33];
    const int k0 = blockIdx.y * 32, n0 = blockIdx.x * 32;
    #pragma unroll
    for (int i = 0; i < 4; i++)
        t[threadIdx.y + i * 8][threadIdx.x] =
            W[(size_t)(k0 + threadIdx.y + i * 8) * N + n0 + threadIdx.x];
    __syncthreads();
    #pragma unroll
    for (int i = 0; i < 4; i++) {
        int n = n0 + threadIdx.y + i * 8;
        int k = k0 + threadIdx.x;
        float x = t[threadIdx.x][threadIdx.y + i * 8];
        __nv_bfloat16 h = __float2bfloat16(x);
        hi[(size_t)n * K + k] = h;
        lo[(size_t)n * K + k] = __float2bfloat16(x - __bfloat162float(h));
    }
}

// ---------------- LayerNorm -> split bf16 ----------------
__global__ void __launch_bounds__(256) ln_kernel(const float* __restrict__ x,
                                                 const float* __restrict__ w,
                                                 const float* __restrict__ b,
                                                 __nv_bfloat16* __restrict__ yhi,
                                                 __nv_bfloat16* __restrict__ ylo) {
    const int row = blockIdx.x;
    const float* xr = x + (size_t)row * D_;
    const int tid = threadIdx.x;

    float v0 = xr[tid], v1 = xr[tid + 256], v2 = xr[tid + 512];
    float s  = v0 + v1 + v2;
    float s2 = v0 * v0 + v1 * v1 + v2 * v2;
    #pragma unroll
    for (int o = 16; o > 0; o >>= 1) {
        s  += __shfl_xor_sync(0xffffffffu, s,  o);
        s2 += __shfl_xor_sync(0xffffffffu, s2, o);
    }
    __shared__ float sh[8], sh2[8];
    const int wi = tid >> 5, ln = tid & 31;
    if (ln == 0) { sh[wi] = s; sh2[wi] = s2; }
    __syncthreads();
    if (wi == 0) {
        s  = (ln < 8) ? sh[ln]  : 0.f;
        s2 = (ln < 8) ? sh2[ln] : 0.f;
        #pragma unroll
        for (int o = 4; o > 0; o >>= 1) {
            s  += __shfl_xor_sync(0xffffffffu, s,  o);
            s2 += __shfl_xor_sync(0xffffffffu, s2, o);
        }
        if (ln == 0) { sh[0] = s; sh2[0] = s2; }
    }
    __syncthreads();
    const float mu  = sh[0] * (1.0f / D_);
    const float var = sh2[0] * (1.0f / D_) - mu * mu;
    const float rs  = rsqrtf(var + 1e-6f);
    size_t base = (size_t)row * D_;
    #pragma unroll
    for (int j = 0; j < 3; j++) {
        int c = tid + j * 256;
        float v = (j == 0 ? v0 : (j == 1 ? v1 : v2));
        float y = (v - mu) * rs * w[c] + b[c];
        __nv_bfloat16 h = __float2bfloat16(y);
        yhi[base + c] = h;
        ylo[base + c] = __float2bfloat16(y - __bfloat162float(h));
    }
}

// ================= linear GEMM: 128x128 CTA, 8 warps of 32x64, BK=32, 2-stage, occ=2 =================
// stage: Ahi@0, Alo@10240, Bhi@20480, Blo@30720; stage=40960 (rows stride 80B)
#define STG 40960u
template <int ACT, bool RES, bool OSPLIT>
__global__ void __launch_bounds__(256, 2) gemm_lin(
    const __nv_bfloat16* __restrict__ Ahi, const __nv_bfloat16* __restrict__ Alo,
    const __nv_bfloat16* __restrict__ Whi, const __nv_bfloat16* __restrict__ Wlo,
    const float* __restrict__ bias, const float* __restrict__ res,
    float* __restrict__ C, __nv_bfloat16* __restrict__ Chi, __nv_bfloat16* __restrict__ Clo,
    int M, int N, int K) {
    extern __shared__ char dsm[];
    const uint32_t sb = smem_u32(dsm);
    const int tid = threadIdx.x;
    const int lane = tid & 31, wid = tid >> 5;
    const int m0 = blockIdx.y * 128, n0 = blockIdx.x * 128;
    const int wm = (wid & 3) * 32, wn = (wid >> 2) * 64;
    const int lrow = tid >> 2;
    const int lq   = (tid & 3) * 16;
    const int mi = lane >> 3, r8 = lane & 7;
    const uint32_t aoff = (uint32_t)((wm + (mi & 1) * 8 + r8) * 80 + ((mi >> 1) * 8) * 2);
    const uint32_t boff = (uint32_t)((wn + (mi >> 1) * 8 + r8) * 80 + ((mi & 1) * 8) * 2);

    float acc[2][8][4];
    #pragma unroll
    for (int a = 0; a < 2; a++)
        #pragma unroll
        for (int b = 0; b < 8; b++)
            #pragma unroll
            for (int d = 0; d < 4; d++) acc[a][b][d] = 0.f;

    const int nc = K >> 5;

    auto load_chunk = [&](int c) {
        const uint32_t st = sb + (uint32_t)(c & 1) * STG;
        const int k0 = c << 5;
        #pragma unroll
        for (int i = 0; i < 2; i++) {
            int r = lrow + i * 64;
            int gr = m0 + r; if (gr > M - 1) gr = M - 1;
            uint32_t d = st + (uint32_t)(r * 80) + lq;
            cp16(d,          (const char*)(Ahi + (size_t)gr * K + k0) + lq);
            cp16(d + 10240u, (const char*)(Alo + (size_t)gr * K + k0) + lq);
            size_t gb = (size_t)(n0 + r) * K + k0;
            cp16(d + 20480u, (const char*)(Whi + gb) + lq);
            cp16(d + 30720u, (const char*)(Wlo + gb) + lq);
        }
    };

    load_chunk(0); CP_COMMIT();

    for (int c = 0; c < nc; c++) {
        if (c + 1 < nc) { load_chunk(c + 1); CP_COMMIT(); CP_WAIT(1); }
        else            { CP_WAIT(0); }
        __syncthreads();
        const uint32_t st = sb + (uint32_t)(c & 1) * STG;
        #pragma unroll
        for (int kb = 0; kb < 2; kb++) {
            const uint32_t ko = (uint32_t)(kb * 32);
            uint32_t ah[2][4], al[2][4];
            ldsm4(ah[0], st + aoff + ko);
            ldsm4(ah[1], st + aoff + 1280u + ko);
            ldsm4(al[0], st + 10240u + aoff + ko);
            ldsm4(al[1], st + 10240u + aoff + 1280u + ko);
            #pragma unroll
            for (int p = 0; p < 4; p++) {
                uint32_t bh[4], bl[4];
                ldsm4(bh, st + 20480u + boff + (uint32_t)(p * 1280) + ko);
                ldsm4(bl, st + 30720u + boff + (uint32_t)(p * 1280) + ko);
                #pragma unroll
                for (int mt = 0; mt < 2; mt++) {
                    mma16816(acc[mt][2 * p],     ah[mt], bh[0], bh[1]);
                    mma16816(acc[mt][2 * p],     ah[mt], bl[0], bl[1]);
                    mma16816(acc[mt][2 * p],     al[mt], bh[0], bh[1]);
                    mma16816(acc[mt][2 * p + 1], ah[mt], bh[2], bh[3]);
                    mma16816(acc[mt][2 * p + 1], ah[mt], bl[2], bl[3]);
                    mma16816(acc[mt][2 * p + 1], al[mt], bh[2], bh[3]);
                }
            }
        }
        __syncthreads();
    }

    // epilogue
    const int g = lane >> 2, tg = lane & 3;
    #pragma unroll
    for (int mt = 0; mt < 2; mt++) {
        const int rb = m0 + wm + mt * 16 + g;
        #pragma unroll
        for (int nt = 0; nt < 8; nt++) {
            const int col = n0 + wn + nt * 8 + tg * 2;
            const float bv0 = bias[col], bv1 = bias[col + 1];
            #pragma unroll
            for (int hh = 0; hh < 2; hh++) {
                const int row = rb + hh * 8;
                if (row < M) {
                    float v0 = acc[mt][nt][hh * 2]     + bv0;
                    float v1 = acc[mt][nt][hh * 2 + 1] + bv1;
                    if (ACT == 1) { v0 = v0 * normcdff(v0); v1 = v1 * normcdff(v1); }
                    size_t go = (size_t)row * N + col;
                    if (RES) {
                        float2 r2 = *(const float2*)(res + go);
                        v0 += r2.x; v1 += r2.y;
                    }
                    if (OSPLIT) {
                        __nv_bfloat162 h2, l2;
                        h2.x = __float2bfloat16(v0); h2.y = __float2bfloat16(v1);
                        l2.x = __float2bfloat16(v0 - __bfloat162float(h2.x));
                        l2.y = __float2bfloat16(v1 - __bfloat162float(h2.y));
                        *(__nv_bfloat162*)(Chi + go) = h2;
                        *(__nv_bfloat162*)(Clo + go) = l2;
                    } else {
                        *(float2*)(C + go) = make_float2(v0, v1);
                    }
                }
            }
        }
    }
}

// ================= scores: 128x128 tile, K=64 in two preloaded chunks, occ=2 =================
__global__ void __launch_bounds__(256, 2) scores_mma(
    const __nv_bfloat16* __restrict__ qkvh, const __nv_bfloat16* __restrict__ qkvl,
    float* __restrict__ dp) {
    extern __shared__ char dsm[];
    const uint32_t sb = smem_u32(dsm);
    const int bh = blockIdx.z;
    const int bb = bh / NH, h = bh % NH;
    const size_t qb = (size_t)bb * T_ * 2304 + h * 64;
    const size_t kb_ = qb + 768;
    float* Cp = dp + (size_t)bh * PTT;
    const int m0 = blockIdx.y * 128, n0 = blockIdx.x * 128;

    const int tid = threadIdx.x;
    const int lane = tid & 31, wid = tid >> 5;
    const int wm = (wid & 3) * 32, wn = (wid >> 2) * 64;
    const int lrow = tid >> 2;
    const int lq   = (tid & 3) * 16;
    const int mi = lane >> 3, r8 = lane & 7;
    const uint32_t aoff = (uint32_t)((wm + (mi & 1) * 8 + r8) * 80 + ((mi >> 1) * 8) * 2);
    const uint32_t boff = (uint32_t)((wn + (mi >> 1) * 8 + r8) * 80 + ((mi & 1) * 8) * 2);

    float acc[2][8][4];
    #pragma unroll
    for (int a = 0; a < 2; a++)
        #pragma unroll
        for (int b = 0; b < 8; b++)
            #pragma unroll
            for (int d = 0; d < 4; d++) acc[a][b][d] = 0.f;

    auto load_chunk = [&](int c) {
        const uint32_t st = sb + (uint32_t)c * STG;
        const int k0 = c << 5;
        #pragma unroll
        for (int i = 0; i < 2; i++) {
            int r = lrow + i * 64;
            int gq = m0 + r; if (gq > T_ - 1) gq = T_ - 1;
            int gk = n0 + r; if (gk > T_ - 1) gk = T_ - 1;
            uint32_t d = st + (uint32_t)(r * 80) + lq;
            cp16(d,          (const char*)(qkvh + qb  + (size_t)gq * 2304 + k0) + lq);
            cp16(d + 10240u, (const char*)(qkvl + qb  + (size_t)gq * 2304 + k0) + lq);
            cp16(d + 20480u, (const char*)(qkvh + kb_ + (size_t)gk * 2304 + k0) + lq);
            cp16(d + 30720u, (const char*)(qkvl + kb_ + (size_t)gk * 2304 + k0) + lq);
        }
    };

    load_chunk(0); CP_COMMIT();
    load_chunk(1); CP_COMMIT();

    #pragma unroll
    for (int c = 0; c < 2; c++) {
        if (c == 0) { CP_WAIT(1); }
        else        { CP_WAIT(0); }
        __syncthreads();
        const uint32_t st = sb + (uint32_t)c * STG;
        #pragma unroll
        for (int kb = 0; kb < 2; kb++) {
            const uint32_t ko = (uint32_t)(kb * 32);
            uint32_t ah[2][4], al[2][4];
            ldsm4(ah[0], st + aoff + ko);
            ldsm4(ah[1], st + aoff + 1280u + ko);
            ldsm4(al[0], st + 10240u + aoff + ko);
            ldsm4(al[1], st + 10240u + aoff + 1280u + ko);
            #pragma unroll
            for (int p = 0; p < 4; p++) {
                uint32_t bh[4], bl[4];
                ldsm4(bh, st + 20480u + boff + (uint32_t)(p * 1280) + ko);
                ldsm4(bl, st + 30720u + boff + (uint32_t)(p * 1280) + ko);
                #pragma unroll
                for (int mt = 0; mt < 2; mt++) {
                    mma16816(acc[mt][2 * p],     ah[mt], bh[0], bh[1]);
                    mma16816(acc[mt][2 * p],     ah[mt], bl[0], bl[1]);
                    mma16816(acc[mt][2 * p],     al[mt], bh[0], bh[1]);
                    mma16816(acc[mt][2 * p + 1], ah[mt], bh[2], bh[3]);
                    mma16816(acc[mt][2 * p + 1], ah[mt], bl[2], bl[3]);
                    mma16816(acc[mt][2 * p + 1], al[mt], bh[2], bh[3]);
                }
            }
        }
    }

    const int g = lane >> 2, tg = lane & 3;
    #pragma unroll
    for (int mt = 0; mt < 2; mt++) {
        const int rb = m0 + wm + mt * 16 + g;
        #pragma unroll
        for (int nt = 0; nt < 8; nt++) {
            const int col = n0 + wn + nt * 8 + tg * 2;
            #pragma unroll
            for (int hh = 0; hh < 2; hh++) {
                const int row = rb + hh * 8;
                if (row < T_ && col < T_) {
                    float v0 = acc[mt][nt][hh * 2]     * 0.125f;
                    float v1 = acc[mt][nt][hh * 2 + 1] * 0.125f;
                    size_t go = (size_t)row * KPAD + col;
                    if (col + 1 < T_) *(float2*)(Cp + go) = make_float2(v0, v1);
                    else Cp[go] = v0;
                }
            }
        }
    }
}

// ---------------- softmax over HEADS -> split bf16 probs (x4 vectorized) ----------------
__global__ void softmax_split(const float* __restrict__ dp,
                              __nv_bfloat16* __restrict__ phi,
                              __nv_bfloat16* __restrict__ plo) {
    long long idx = (long long)blockIdx.x * blockDim.x + threadIdx.x;
    const long long tot = (long long)B_ * (PTT / 4);
    if (idx >= tot) return;
    const int b  = (int)(idx / (PTT / 4));
    const int r4 = (int)(idx % (PTT / 4));
    size_t base = (size_t)b * NH * PTT + (size_t)r4 * 4;
    float4 v[NH];
    float4 mx = make_float4(-1e30f, -1e30f, -1e30f, -1e30f);
    #pragma unroll
    for (int h = 0; h < NH; h++) {
        v[h] = *(const float4*)(dp + base + (size_t)h * PTT);
        mx.x = fmaxf(mx.x, v[h].x); mx.y = fmaxf(mx.y, v[h].y);
        mx.z = fmaxf(mx.z, v[h].z); mx.w = fmaxf(mx.w, v[h].w);
    }
    float4 s = make_float4(0.f, 0.f, 0.f, 0.f);
    #pragma unroll
    for (int h = 0; h < NH; h++) {
        v[h].x = expf(v[h].x - mx.x); s.x += v[h].x;
        v[h].y = expf(v[h].y - mx.y); s.y += v[h].y;
        v[h].z = expf(v[h].z - mx.z); s.z += v[h].z;
        v[h].w = expf(v[h].w - mx.w); s.w += v[h].w;
    }
    s.x = 1.f / s.x; s.y = 1.f / s.y; s.z = 1.f / s.z; s.w = 1.f / s.w;
    #pragma unroll
    for (int h = 0; h < NH; h++) {
        float p0 = v[h].x * s.x, p1 = v[h].y * s.y, p2 = v[h].z * s.z, p3 = v[h].w * s.w;
        __nv_bfloat162 h0, h1, l0, l1;
        h0.x = __float2bfloat16(p0); h0.y = __float2bfloat16(p1);
        h1.x = __float2bfloat16(p2); h1.y = __float2bfloat16(p3);
        l0.x = __float2bfloat16(p0 - __bfloat162float(h0.x));
        l0.y = __float2bfloat16(p1 - __bfloat162float(h0.y));
        l1.x = __float2bfloat16(p2 - __bfloat162float(h1.x));
        l1.y = __float2bfloat16(p3 - __bfloat162float(h1.y));
        size_t o = base + (size_t)h * PTT;
        *(__nv_bfloat162*)(phi + o)     = h0;
        *(__nv_bfloat162*)(phi + o + 2) = h1;
        *(__nv_bfloat162*)(plo + o)     = l0;
        *(__nv_bfloat162*)(plo + o + 2) = l1;
    }
}

// ---------------- wa = probs @ V (HMMA, ldmatrix.trans for V), occ=2 ----------------
#define STGW 29696u
__global__ void __launch_bounds__(256, 2) wa_mma(
    const __nv_bfloat16* __restrict__ phi, const __nv_bfloat16* __restrict__ plo,
    const __nv_bfloat16* __restrict__ qkvh, const __nv_bfloat16* __restrict__ qkvl,
    __nv_bfloat16* __restrict__ whi, __nv_bfloat16* __restrict__ wlo) {
    extern __shared__ char dsm[];
    const uint32_t sb = smem_u32(dsm);
    const int tid = threadIdx.x;
    const int lane = tid & 31, wid = tid >> 5;
    const int bh = blockIdx.y;
    const int b = bh / NH, h = bh % NH;
    const int q0 = blockIdx.x * 128;
    const int wm = (wid & 3) * 32, wn = (wid >> 2) * 32;
    const int lrow = tid >> 2;
    const int lq   = (tid & 3) * 16;
    const int mi = lane >> 3, r8 = lane & 7;
    const uint32_t aoff = (uint32_t)((wm + (mi & 1) * 8 + r8) * 80 + ((mi >> 1) * 8) * 2);
    const uint32_t voff = (uint32_t)(((mi & 1) * 8 + r8) * 144 + (wn + (mi >> 1) * 8) * 2);

    const size_t pbase = (size_t)bh * PTT;
    const size_t vbase = (size_t)b * T_ * 2304 + 1536 + h * 64;

    float acc[2][4][4];
    #pragma unroll
    for (int a = 0; a < 2; a++)
        #pragma unroll
        for (int n = 0; n < 4; n++)
            #pragma unroll
            for (int d = 0; d < 4; d++) acc[a][n][d] = 0.f;

    const int nc = (T_ + 31) / 32;  // 19

    auto load_chunk = [&](int c) {
        const uint32_t st = sb + (uint32_t)(c % 3) * STGW;
        const int k0 = c * 32;
        #pragma unroll
        for (int i = 0; i < 2; i++) {
            int r = lrow + i * 64;
            int q = q0 + r; if (q > T_ - 1) q = T_ - 1;
            int kstart = k0 + (lq >> 1);
            int nb = (T_ - kstart) * 2;
            nb = nb < 0 ? 0 : (nb > 16 ? 16 : nb);
            size_t off = pbase + (size_t)q * KPAD + k0;
            uint32_t d = st + (uint32_t)(r * 80) + lq;
            cp16z(d,          (const char*)(phi + off) + lq, nb);
            cp16z(d + 10240u, (const char*)(plo + off) + lq, nb);
        }
        {
            int vr = tid >> 3, vq = (tid & 7) * 16;
            int k = k0 + vr;
            int nb = (k < T_) ? 16 : 0;
            if (k > T_ - 1) k = T_ - 1;
            size_t off = vbase + (size_t)k * 2304;
            uint32_t d = st + 20480u + (uint32_t)(vr * 144) + vq;
            cp16z(d,         (const char*)(qkvh + off) + vq, nb);
            cp16z(d + 4608u, (const char*)(qkvl + off) + vq, nb);
        }
    };

    load_chunk(0); CP_COMMIT();
    load_chunk(1); CP_COMMIT();

    for (int c = 0; c < nc; c++) {
        CP_WAIT(1);
        __syncthreads();
        const uint32_t st = sb + (uint32_t)(c % 3) * STGW;
        #pragma unroll
        for (int ks = 0; ks < 2; ks++) {
            const uint32_t ko = (uint32_t)(ks * 32);
            uint32_t ah[2][4], al[2][4];
            ldsm4(ah[0], st + aoff + ko);
            ldsm4(ah[1], st + aoff + 1280u + ko);
            ldsm4(al[0], st + 10240u + aoff + ko);
            ldsm4(al[1], st + 10240u + aoff + 1280u + ko);
            uint32_t vh0[4], vh1[4], vl0[4], vl1[4];
            const uint32_t vb = st + 20480u + voff + (uint32_t)(ks * 2304);
            ldsm4t(vh0, vb);
            ldsm4t(vh1, vb + 32u);
            ldsm4t(vl0, vb + 4608u);
            ldsm4t(vl1, vb + 4608u + 32u);
            #pragma unroll
            for (int mt = 0; mt < 2; mt++) {
                mma16816(acc[mt][0], ah[mt], vh0[0], vh0[1]);
                mma16816(acc[mt][0], ah[mt], vl0[0], vl0[1]);
                mma16816(acc[mt][0], al[mt], vh0[0], vh0[1]);
                mma16816(acc[mt][1], ah[mt], vh0[2], vh0[3]);
                mma16816(acc[mt][1], ah[mt], vl0[2], vl0[3]);
                mma16816(acc[mt][1], al[mt], vh0[2], vh0[3]);
                mma16816(acc[mt][2], ah[mt], vh1[0], vh1[1]);
                mma16816(acc[mt][2], ah[mt], vl1[0], vl1[1]);
                mma16816(acc[mt][2], al[mt], vh1[0], vh1[1]);
                mma16816(acc[mt][3], ah[mt], vh1[2], vh1[3]);
                mma16816(acc[mt][3], ah[mt], vl1[2], vl1[3]);
                mma16816(acc[mt][3], al[mt], vh1[2], vh1[3]);
            }
        }
        if (c + 2 < nc) load_chunk(c + 2);
        CP_COMMIT();
    }

    const int g = lane >> 2, tg = lane & 3;
    #pragma unroll
    for (int mt = 0; mt < 2; mt++) {
        #pragma unroll
        for (int nt = 0; nt < 4; nt++) {
            const int col = wn + nt * 8 + tg * 2;
            #pragma unroll
            for (int hh = 0; hh < 2; hh++) {
                const int row = q0 + wm + mt * 16 + g + hh * 8;
                if (row < T_) {
                    float v0 = acc[mt][nt][hh * 2];
                    float v1 = acc[mt][nt][hh * 2 + 1];
                    size_t go = ((size_t)(b * T_ + row)) * D_ + h * 64 + col;
                    __nv_bfloat162 h2, l2;
                    h2.x = __float2bfloat16(v0); h2.y = __float2bfloat16(v1);
                    l2.x = __float2bfloat16(v0 - __bfloat162float(h2.x));
                    l2.y = __float2bfloat16(v1 - __bfloat162float(h2.y));
                    *(__nv_bfloat162*)(whi + go) = h2;
                    *(__nv_bfloat162*)(wlo + go) = l2;
                }
            }
        }
    }
}

// ---------------- host launch ----------------
extern "C" void kernel_launch(void* const* d_in, const int* in_sizes, int n_in,
                              void* d_out, int out_size) {
    const float* x      = (const float*)d_in[0];
    const float* ln1_w  = (const float*)d_in[1];
    const float* ln1_b  = (const float*)d_in[2];
    const float* qkv_w  = (const float*)d_in[3];
    const float* qkv_b  = (const float*)d_in[4];
    const float* proj_w = (const float*)d_in[5];
    const float* proj_b = (const float*)d_in[6];
    const float* ln2_w  = (const float*)d_in[7];
    const float* ln2_b  = (const float*)d_in[8];
    const float* fc1_w  = (const float*)d_in[9];
    const float* fc1_b  = (const float*)d_in[10];
    const float* fc2_w  = (const float*)d_in[11];
    const float* fc2_b  = (const float*)d_in[12];
    float* out = (float*)d_out;

    __nv_bfloat16 *yhi, *ylo, *qkh, *qkl, *ph, *pl, *wahi, *walo, *hhi, *hlo;
    __nv_bfloat16 *wqh, *wql, *wph, *wpl, *w1h, *w1l, *w2h, *w2l;
    float *dpb, *x1b;
    cudaGetSymbolAddress((void**)&yhi,  g_y_hi);
    cudaGetSymbolAddress((void**)&ylo,  g_y_lo);
    cudaGetSymbolAddress((void**)&qkh,  g_qkv_hi);
    cudaGetSymbolAddress((void**)&qkl,  g_qkv_lo);
    cudaGetSymbolAddress((void**)&dpb,  g_dp);
    cudaGetSymbolAddress((void**)&ph,   g_p_hi);
    cudaGetSymbolAddress((void**)&pl,   g_p_lo);
    cudaGetSymbolAddress((void**)&wahi, g_wa_hi);
    cudaGetSymbolAddress((void**)&walo, g_wa_lo);
    cudaGetSymbolAddress((void**)&x1b,  g_x1);
    cudaGetSymbolAddress((void**)&hhi,  g_h_hi);
    cudaGetSymbolAddress((void**)&hlo,  g_h_lo);
    cudaGetSymbolAddress((void**)&wqh,  g_wq_hi);
    cudaGetSymbolAddress((void**)&wql,  g_wq_lo);
    cudaGetSymbolAddress((void**)&wph,  g_wp_hi);
    cudaGetSymbolAddress((void**)&wpl,  g_wp_lo);
    cudaGetSymbolAddress((void**)&w1h,  g_w1_hi);
    cudaGetSymbolAddress((void**)&w1l,  g_w1_lo);
    cudaGetSymbolAddress((void**)&w2h,  g_w2_hi);
    cudaGetSymbolAddress((void**)&w2l,  g_w2_lo);

    const int SMEM_L = 2 * (int)STG;       // 81920
    const int SMEM_S = 2 * (int)STG;       // 81920
    const int SMEM_W = 3 * (int)STGW;      // 89088
    cudaFuncSetAttribute(gemm_lin<0, false, true >, cudaFuncAttributeMaxDynamicSharedMemorySize, SMEM_L);
    cudaFuncSetAttribute(gemm_lin<0, true,  false>, cudaFuncAttributeMaxDynamicSharedMemorySize, SMEM_L);
    cudaFuncSetAttribute(gemm_lin<1, false, true >, cudaFuncAttributeMaxDynamicSharedMemorySize, SMEM_L);
    cudaFuncSetAttribute(scores_mma, cudaFuncAttributeMaxDynamicSharedMemorySize, SMEM_S);
    cudaFuncSetAttribute(wa_mma,     cudaFuncAttributeMaxDynamicSharedMemorySize, SMEM_W);

    const int MT = (BT + 127) / 128;  // 145

    wconv_kernel<<<dim3(2304 / 32, 768 / 32),  dim3(32, 8)>>>(qkv_w,  wqh, wql, 768,  2304);
    wconv_kernel<<<dim3(768 / 32,  768 / 32),  dim3(32, 8)>>>(proj_w, wph, wpl, 768,  768);
    wconv_kernel<<<dim3(3072 / 32, 768 / 32),  dim3(32, 8)>>>(fc1_w,  w1h, w1l, 768,  3072);
    wconv_kernel<<<dim3(768 / 32,  3072 / 32), dim3(32, 8)>>>(fc2_w,  w2h, w2l, 3072, 768);

    // 1) LN1 -> split
    ln_kernel<<<BT, 256>>>(x, ln1_w, ln1_b, yhi, ylo);
    // 2) QKV projection -> split bf16 qkv
    gemm_lin<0, false, true><<<dim3(2304 / 128, MT), 256, SMEM_L>>>(
        yhi, ylo, wqh, wql, qkv_b, nullptr, nullptr, qkh, qkl, BT, 2304, D_);
    // 3) scores -> fp32 dp (padded rows)
    scores_mma<<<dim3(5, 5, B_ * NH), 256, SMEM_S>>>(qkh, qkl, dpb);
    // 4) softmax over heads -> split bf16 probs
    {
        long long total = (long long)B_ * (PTT / 4);
        int grid = (int)((total + 255) / 256);
        softmax_split<<<grid, 256>>>(dpb, ph, pl);
    }
    // 5) wa = probs @ V -> split
    wa_mma<<<dim3(5, B_ * NH), 256, SMEM_W>>>(ph, pl, qkh, qkl, wahi, walo);
    // 6) output projection + residual
    gemm_lin<0, true, false><<<dim3(D_ / 128, MT), 256, SMEM_L>>>(
        wahi, walo, wph, wpl, proj_b, x, x1b, nullptr, nullptr, BT, D_, D_);
    // 7) LN2 -> split
    ln_kernel<<<BT, 256>>>(x1b, ln2_w, ln2_b, yhi, ylo);
    // 8) fc1 + exact GELU -> split
    gemm_lin<1, false, true><<<dim3(H_ / 128, MT), 256, SMEM_L>>>(
        yhi, ylo, w1h, w1l, fc1_b, nullptr, nullptr, hhi, hlo, BT, H_, D_);
    // 9) fc2 + residual -> output
    gemm_lin<0, true, false><<<dim3(D_ / 128, MT), 256, SMEM_L>>>(
        hhi, hlo, w2h, w2l, fc2_b, x1b, out, nullptr, nullptr, BT, D_, H_);
}